// round 4
// baseline (speedup 1.0000x reference)
#include <cuda_runtime.h>
#include <math.h>

// ---------------- problem constants ----------------
#define NROWS   131072
#define DDIM    256
#define NCODES  1024
#define EPSC    1e-5f
#define DECAYC  0.99f

typedef unsigned long long ull;

// ---------------- output layout (float32, reference tuple order, flattened) ----------------
#define OFF_ZQST 0ULL
#define OFF_ZID  33554432ULL
#define OFF_LOSS 33685504ULL
#define OFF_ZQ   33685505ULL
#define OFF_NEMB 67239937ULL
#define OFF_NCS  67502081ULL
#define OFF_NEA  67503105ULL
#define OFF_PPL  67765249ULL

// ---------------- device scratch (static: no allocation allowed) ----------------
static __device__ float  g_embedn[NCODES * DDIM];   // normalized codebook
static __device__ float  g_rs[NROWS];               // per-row rsqrt(||h||^2)
static __device__ int    g_zid[NROWS];
static __device__ float  g_counts[NCODES];
static __device__ float  g_esum[NCODES * DDIM];
static __device__ double g_losspart[16384];
static __device__ float  g_den[NCODES];
static __device__ int    g_src[NCODES];             // revival source row or -1

// ---------------- small helpers ----------------
__device__ __forceinline__ void fma2(ull& d, ull a, ull b) {
    asm("fma.rn.f32x2 %0, %1, %2, %0;" : "+l"(d) : "l"(a), "l"(b));
}
__device__ __forceinline__ float2 unpack2(ull v) {
    float2 r;
    asm("mov.b64 {%0, %1}, %2;" : "=f"(r.x), "=f"(r.y) : "l"(v));
    return r;
}
__device__ __forceinline__ unsigned rotl32(unsigned x, int r) {
    return (x << r) | (x >> (32 - r));
}

// threefry2x32, FULL 20 rounds (5 groups of 4), canonical injection schedule.
__device__ __forceinline__ void tf2x32(unsigned k0, unsigned k1,
                                       unsigned& x0, unsigned& x1) {
    const unsigned ks2 = 0x1BD11BDAu ^ k0 ^ k1;
#define TF_RND(r) { x0 += x1; x1 = rotl32(x1, (r)); x1 ^= x0; }
    x0 += k0; x1 += k1;
    TF_RND(13) TF_RND(15) TF_RND(26) TF_RND(6)
    x0 += k1;  x1 += ks2 + 1u;
    TF_RND(17) TF_RND(29) TF_RND(16) TF_RND(24)
    x0 += ks2; x1 += k0 + 2u;
    TF_RND(13) TF_RND(15) TF_RND(26) TF_RND(6)
    x0 += k0;  x1 += k1 + 3u;
    TF_RND(17) TF_RND(29) TF_RND(16) TF_RND(24)
    x0 += k1;  x1 += ks2 + 4u;
    TF_RND(13) TF_RND(15) TF_RND(26) TF_RND(6)
    x0 += ks2; x1 += k0 + 5u;
#undef TF_RND
}

// jax.random.randint(key(42), (1024,), 0, 131072)[i]  with
// jax_threefry_partitionable = True (JAX >= 0.5 default):
//   split (fold-like): counts = iota_2x32 over (2,) -> lane i ctr (hi=0, lo=i);
//     new key i = (y0, y1) of that lane. k2 = threefry((0,42), (0,1)).
//   random_bits (partitionable, 32-bit): per element i, ctr (hi=0, lo=i);
//     bits = y0 ^ y1 (XOR-fold of the 64-bit threefry output).
//   span = 2^17 -> multiplier term vanishes -> idx = bits & 0x1FFFF.
__device__ unsigned jax_randint_idx(int i) {
    unsigned s0 = 0u, s1 = 1u;                 // ctr (0, 1) -> second derived key
    tf2x32(0u, 42u, s0, s1);                   // k2 = (s0, s1)
    unsigned x0 = 0u, x1 = (unsigned)i;        // ctr (0, i)
    tf2x32(s0, s1, x0, x1);
    return (x0 ^ x1) & 0x1FFFFu;
}

// ---------------- kernels ----------------

__global__ void k_zero() {
    int i = blockIdx.x * blockDim.x + threadIdx.x;   // grid covers 262144
    if (i < NCODES * DDIM) g_esum[i] = 0.0f;
    if (i < NCODES)        g_counts[i] = 0.0f;
}

__global__ void k_norm_embed(const float* __restrict__ e) {
    int w = (blockIdx.x * blockDim.x + threadIdx.x) >> 5;
    int lane = threadIdx.x & 31;
    if (w >= NCODES) return;
    const float* row = e + (size_t)w * DDIM;
    float s = 0.0f;
#pragma unroll
    for (int t = 0; t < DDIM / 32; t++) { float v = row[lane + 32 * t]; s += v * v; }
#pragma unroll
    for (int o = 16; o; o >>= 1) s += __shfl_xor_sync(0xFFFFFFFFu, s, o);
    float rs = (float)(1.0 / sqrt((double)fmaxf(s, 1e-12f)));
#pragma unroll
    for (int t = 0; t < DDIM / 32; t++)
        g_embedn[(size_t)w * DDIM + lane + 32 * t] = row[lane + 32 * t] * rs;
}

__global__ void k_norm_h(const float* __restrict__ h) {
    int w = (blockIdx.x * blockDim.x + threadIdx.x) >> 5;
    int lane = threadIdx.x & 31;
    if (w >= NROWS) return;
    const float* row = h + (size_t)w * DDIM;
    float s = 0.0f;
#pragma unroll
    for (int t = 0; t < DDIM / 32; t++) { float v = row[lane + 32 * t]; s += v * v; }
#pragma unroll
    for (int o = 16; o; o >>= 1) s += __shfl_xor_sync(0xFFFFFFFFu, s, o);
    if (lane == 0) g_rs[w] = (float)(1.0 / sqrt((double)fmaxf(s, 1e-12f)));
}

// 128-row x 1024-code argmin GEMM, FP32 via packed f32x2 FMA.
// Block: 256 threads = 16x16; thread tile 8 rows x 8 codes (4 f32x2 pairs).
__global__ __launch_bounds__(256, 2) void k_argmin(const float* __restrict__ h,
                                                   float* __restrict__ out) {
    __shared__ __align__(16) float As[16][256];   // hn, duplicated pairs: [k][2r]=[k][2r+1]
    __shared__ __align__(16) float Bs[16][128];   // en
    __shared__ float rsS[128];
    __shared__ float redV[128 * 16];
    __shared__ int   redI[128 * 16];

    int tid = threadIdx.x;
    int tx = tid & 15, ty = tid >> 4;
    size_t rowBase = (size_t)blockIdx.x * 128;

    if (tid < 128) rsS[tid] = g_rs[rowBase + tid];

    float bestV[8]; int bestI[8];
#pragma unroll
    for (int i = 0; i < 8; i++) { bestV[i] = 3.4e38f; bestI[i] = 0; }

    for (int cc = 0; cc < 8; ++cc) {
        int cBase = cc * 128;
        ull acc[8][4];
#pragma unroll
        for (int i = 0; i < 8; i++)
#pragma unroll
            for (int j = 0; j < 4; j++) acc[i][j] = 0ull;

        for (int kt = 0; kt < 16; ++kt) {
            __syncthreads();
            // fill A (normalized h), duplicated for f32x2 broadcast
#pragma unroll
            for (int q = 0; q < 2; q++) {
                int t2 = tid * 2 + q;           // 0..511
                int r = t2 >> 2, cg = t2 & 3;
                const float4 v = *(const float4*)(h + (rowBase + r) * DDIM + kt * 16 + cg * 4);
                float s = rsS[r];
                float vals[4] = { v.x * s, v.y * s, v.z * s, v.w * s };
#pragma unroll
                for (int e = 0; e < 4; e++) {
                    As[cg * 4 + e][2 * r]     = vals[e];
                    As[cg * 4 + e][2 * r + 1] = vals[e];
                }
            }
            // fill B (normalized codes)
#pragma unroll
            for (int q = 0; q < 2; q++) {
                int t2 = tid * 2 + q;
                int c = t2 >> 2, cg = t2 & 3;
                const float4 v = *(const float4*)(g_embedn + (size_t)(cBase + c) * DDIM + kt * 16 + cg * 4);
                Bs[cg * 4 + 0][c] = v.x; Bs[cg * 4 + 1][c] = v.y;
                Bs[cg * 4 + 2][c] = v.z; Bs[cg * 4 + 3][c] = v.w;
            }
            __syncthreads();
#pragma unroll
            for (int kk = 0; kk < 16; kk++) {
                const ull* ap = (const ull*)&As[kk][0];
                const ull* bp = (const ull*)&Bs[kk][0];
                ull a2[8], b2[4];
#pragma unroll
                for (int i = 0; i < 8; i++) a2[i] = ap[ty * 8 + i];
#pragma unroll
                for (int j = 0; j < 4; j++) b2[j] = bp[tx + 16 * j];  // conflict-free LDS.64
#pragma unroll
                for (int i = 0; i < 8; i++)
#pragma unroll
                    for (int j = 0; j < 4; j++) fma2(acc[i][j], a2[i], b2[j]);
            }
        }
        // fold chunk into running argmin (ascending code order => first-min tie-break)
#pragma unroll
        for (int i = 0; i < 8; i++) {
#pragma unroll
            for (int j = 0; j < 4; j++) {
                float2 dv = unpack2(acc[i][j]);
                int c0 = cBase + 2 * tx + 32 * j;
                float d0 = 1.0f - dv.x;
                if (d0 < bestV[i]) { bestV[i] = d0; bestI[i] = c0; }
                float d1 = 1.0f - dv.y;
                if (d1 < bestV[i]) { bestV[i] = d1; bestI[i] = c0 + 1; }
            }
        }
    }

    __syncthreads();
#pragma unroll
    for (int i = 0; i < 8; i++) {
        int r = ty * 8 + i;
        redV[r * 16 + tx] = bestV[i];
        redI[r * 16 + tx] = bestI[i];
    }
    __syncthreads();
    if (tid < 128) {
        float bv = redV[tid * 16]; int bi = redI[tid * 16];
#pragma unroll
        for (int t = 1; t < 16; t++) {
            float v = redV[tid * 16 + t]; int ix = redI[tid * 16 + t];
            if (v < bv || (v == bv && ix < bi)) { bv = v; bi = ix; }
        }
        g_zid[rowBase + tid] = bi;
        out[OFF_ZID + rowBase + tid] = (float)bi;
    }
}

// per-row: z_q gather, z_q_st, commit-loss partials, counts, embed_sum scatter
__global__ __launch_bounds__(256) void k_assign(const float* __restrict__ h,
                                                const float* __restrict__ embed,
                                                float* __restrict__ out) {
    __shared__ float wsum[8];
    int lane = threadIdx.x & 31, w = threadIdx.x >> 5;
    size_t row = (size_t)blockIdx.x * 8 + w;
    int code = g_zid[row];
    const float* hr = h + row * DDIM;
    const float* er = embed + (size_t)code * DDIM;
    float acc = 0.0f;
#pragma unroll
    for (int t = 0; t < DDIM / 32; t++) {
        int d = lane + 32 * t;
        float hv = hr[d], ev = er[d];
        out[OFF_ZQ + row * DDIM + d] = ev;
        out[OFF_ZQST + row * DDIM + d] = hv + (ev - hv);
        float df = hv - ev;
        acc += df * df;
        atomicAdd(&g_esum[(size_t)code * DDIM + d], hv);
    }
#pragma unroll
    for (int o = 16; o; o >>= 1) acc += __shfl_xor_sync(0xFFFFFFFFu, acc, o);
    if (lane == 0) {
        wsum[w] = acc;
        atomicAdd(&g_counts[code], 1.0f);
    }
    __syncthreads();
    if (threadIdx.x == 0) {
        double s = 0.0;
#pragma unroll
        for (int i = 0; i < 8; i++) s += (double)wsum[i];
        g_losspart[blockIdx.x] = s;
    }
}

// per-code scalars: EMA counts, smoothing, dead detection + threefry revival idx,
// loss, entropy/perplexity. Single block of 1024 threads.
__global__ void k_final_a(const float* __restrict__ cs_in, float* __restrict__ out) {
    __shared__ double sd[1024];
    int t = threadIdx.x;
    float c = g_counts[t];
    float ncs = cs_in[t] * DECAYC + c * (1.0f - DECAYC);

    // n = sum(new_cs)
    sd[t] = (double)ncs; __syncthreads();
    for (int o = 512; o; o >>= 1) { if (t < o) sd[t] += sd[t + o]; __syncthreads(); }
    double n = sd[0]; __syncthreads();

    // entropy
    float usage = c / 131072.0f;
    float term = (usage > 0.0f) ? usage * logf(usage) : 0.0f;
    sd[t] = (double)term; __syncthreads();
    for (int o = 512; o; o >>= 1) { if (t < o) sd[t] += sd[t + o]; __syncthreads(); }
    float ent = -(float)sd[0]; __syncthreads();

    // commit loss
    double lp = 0.0;
    for (int i = t; i < 16384; i += 1024) lp += g_losspart[i];
    sd[t] = lp; __syncthreads();
    for (int o = 512; o; o >>= 1) { if (t < o) sd[t] += sd[t + o]; __syncthreads(); }
    double loss_sum = sd[0];

    float nf = (float)n;
    float meanv = (float)(n / 1024.0);
    float cs_sm = (ncs + EPSC) / (nf + 1024.0f * EPSC) * nf;
    float den = fmaxf(cs_sm, EPSC);
    bool dead = (ncs / (131072.0f + EPSC)) < 0.01f;

    g_den[t] = den;
    g_src[t] = dead ? (int)jax_randint_idx(t) : -1;
    out[OFF_NCS + t] = dead ? fmaxf(meanv, 1.0f) : ncs;

    if (t == 0) {
        out[OFF_LOSS] = (float)(loss_sum / (double)((size_t)NROWS * DDIM)); // COMMIT_W=1
        out[OFF_PPL]  = expf(ent);
    }
}

// per-code rows: new_ea, new_embed (with revival gather)
__global__ void k_final_b(const float* __restrict__ h, const float* __restrict__ ea_in,
                          float* __restrict__ out) {
    int k = blockIdx.x;          // 1024 blocks
    int d = threadIdx.x;         // 256 threads
    size_t idx = (size_t)k * DDIM + d;
    float nea = ea_in[idx] * DECAYC + g_esum[idx] * (1.0f - DECAYC);
    out[OFF_NEA + idx] = nea;
    int src = g_src[k];
    float ne = (src >= 0) ? h[(size_t)src * DDIM + d] : nea / g_den[k];
    out[OFF_NEMB + idx] = ne;
}

// ---------------- launch ----------------
extern "C" void kernel_launch(void* const* d_in, const int* in_sizes, int n_in,
                              void* d_out, int out_size) {
    const float* h     = (const float*)d_in[0];
    const float* embed = (const float*)d_in[1];
    const float* cs    = (const float*)d_in[2];
    const float* ea    = (const float*)d_in[3];
    float* out = (float*)d_out;

    k_zero<<<1024, 256>>>();
    k_norm_embed<<<128, 256>>>(embed);     // 1024 warps
    k_norm_h<<<16384, 256>>>(h);           // 131072 warps
    k_argmin<<<1024, 256>>>(h, out);       // 128 rows/block
    k_assign<<<16384, 256>>>(h, embed, out);
    k_final_a<<<1, 1024>>>(cs, out);
    k_final_b<<<1024, 256>>>(h, ea, out);
}

// round 6
// speedup vs baseline: 1.1607x; 1.1607x over previous
#include <cuda_runtime.h>
#include <math.h>

// ---------------- problem constants ----------------
#define NROWS   131072
#define DDIM    256
#define NCODES  1024
#define EPSC    1e-5f
#define DECAYC  0.99f

typedef unsigned long long ull;

// ---------------- output layout (float32, reference tuple order, flattened) ----------------
#define OFF_ZQST 0ULL
#define OFF_ZID  33554432ULL
#define OFF_LOSS 33685504ULL
#define OFF_ZQ   33685505ULL
#define OFF_NEMB 67239937ULL
#define OFF_NCS  67502081ULL
#define OFF_NEA  67503105ULL
#define OFF_PPL  67765249ULL

// ---------------- device scratch (static: no allocation allowed) ----------------
static __device__ float  g_embedn[NCODES * DDIM];   // normalized codebook
static __device__ float  g_rs[NROWS];               // per-row rsqrt(||h||^2)
static __device__ int    g_zid[NROWS];
static __device__ float  g_counts[NCODES];
static __device__ float  g_esum[NCODES * DDIM];
static __device__ double g_losspart[16384];
static __device__ float  g_den[NCODES];
static __device__ int    g_src[NCODES];             // revival source row or -1

// ---------------- small helpers ----------------
__device__ __forceinline__ void fma2(ull& d, ull a, ull b) {
    asm("fma.rn.f32x2 %0, %1, %2, %0;" : "+l"(d) : "l"(a), "l"(b));
}
__device__ __forceinline__ ull dup2(float v) {
    ull r; unsigned u = __float_as_uint(v);
    asm("mov.b64 %0, {%1, %1};" : "=l"(r) : "r"(u));
    return r;
}
__device__ __forceinline__ float2 unpack2(ull v) {
    float2 r;
    asm("mov.b64 {%0, %1}, %2;" : "=f"(r.x), "=f"(r.y) : "l"(v));
    return r;
}
__device__ __forceinline__ unsigned rotl32(unsigned x, int r) {
    return (x << r) | (x >> (32 - r));
}

// threefry2x32, FULL 20 rounds (5 groups of 4), canonical injection schedule.
__device__ __forceinline__ void tf2x32(unsigned k0, unsigned k1,
                                       unsigned& x0, unsigned& x1) {
    const unsigned ks2 = 0x1BD11BDAu ^ k0 ^ k1;
#define TF_RND(r) { x0 += x1; x1 = rotl32(x1, (r)); x1 ^= x0; }
    x0 += k0; x1 += k1;
    TF_RND(13) TF_RND(15) TF_RND(26) TF_RND(6)
    x0 += k1;  x1 += ks2 + 1u;
    TF_RND(17) TF_RND(29) TF_RND(16) TF_RND(24)
    x0 += ks2; x1 += k0 + 2u;
    TF_RND(13) TF_RND(15) TF_RND(26) TF_RND(6)
    x0 += k0;  x1 += k1 + 3u;
    TF_RND(17) TF_RND(29) TF_RND(16) TF_RND(24)
    x0 += k1;  x1 += ks2 + 4u;
    TF_RND(13) TF_RND(15) TF_RND(26) TF_RND(6)
    x0 += ks2; x1 += k0 + 5u;
#undef TF_RND
}

// jax.random.randint(key(42), (1024,), 0, 131072)[i]  with
// jax_threefry_partitionable = True (JAX >= 0.5 default):
//   k2 = threefry((0,42), (0,1));  bits_i = xor-fold(threefry(k2, (0,i)));
//   span = 2^17 -> idx = bits & 0x1FFFF.
__device__ unsigned jax_randint_idx(int i) {
    unsigned s0 = 0u, s1 = 1u;
    tf2x32(0u, 42u, s0, s1);
    unsigned x0 = 0u, x1 = (unsigned)i;
    tf2x32(s0, s1, x0, x1);
    return (x0 ^ x1) & 0x1FFFFu;
}

// ---------------- kernels ----------------

__global__ void k_zero() {
    int i = blockIdx.x * blockDim.x + threadIdx.x;   // grid covers 262144
    if (i < NCODES * DDIM) g_esum[i] = 0.0f;
    if (i < NCODES)        g_counts[i] = 0.0f;
}

__global__ void k_norm_embed(const float* __restrict__ e) {
    int w = (blockIdx.x * blockDim.x + threadIdx.x) >> 5;
    int lane = threadIdx.x & 31;
    if (w >= NCODES) return;
    const float* row = e + (size_t)w * DDIM;
    float s = 0.0f;
#pragma unroll
    for (int t = 0; t < DDIM / 32; t++) { float v = row[lane + 32 * t]; s += v * v; }
#pragma unroll
    for (int o = 16; o; o >>= 1) s += __shfl_xor_sync(0xFFFFFFFFu, s, o);
    float rs = (float)(1.0 / sqrt((double)fmaxf(s, 1e-12f)));
#pragma unroll
    for (int t = 0; t < DDIM / 32; t++)
        g_embedn[(size_t)w * DDIM + lane + 32 * t] = row[lane + 32 * t] * rs;
}

__global__ void k_norm_h(const float* __restrict__ h) {
    int w = (blockIdx.x * blockDim.x + threadIdx.x) >> 5;
    int lane = threadIdx.x & 31;
    if (w >= NROWS) return;
    const float4* row = (const float4*)(h + (size_t)w * DDIM);
    float s = 0.0f;
#pragma unroll
    for (int t = 0; t < 2; t++) {
        float4 v = row[lane + 32 * t];
        s += v.x * v.x + v.y * v.y + v.z * v.z + v.w * v.w;
    }
#pragma unroll
    for (int o = 16; o; o >>= 1) s += __shfl_xor_sync(0xFFFFFFFFu, s, o);
    if (lane == 0) g_rs[w] = (float)(1.0 / sqrt((double)fmaxf(s, 1e-12f)));
}

// 128-row x 1024-code argmin GEMM, FP32 via packed f32x2 FMA.
// Block: 256 threads = 16x16; thread tile 8 rows x 8 codes (4 f32x2 pairs).
// A stored UNduplicated in smem; duplication into f32x2 happens in registers.
__global__ __launch_bounds__(256, 2) void k_argmin(const float* __restrict__ h,
                                                   float* __restrict__ out) {
    __shared__ __align__(16) float As[16][128];   // normalized h rows (k-major)
    __shared__ __align__(16) float Bs[16][128];   // normalized codes
    __shared__ float rsS[128];
    __shared__ float redV[128 * 16];
    __shared__ int   redI[128 * 16];

    int tid = threadIdx.x;
    int tx = tid & 15, ty = tid >> 4;
    size_t rowBase = (size_t)blockIdx.x * 128;

    if (tid < 128) rsS[tid] = g_rs[rowBase + tid];

    float bestV[8]; int bestI[8];
#pragma unroll
    for (int i = 0; i < 8; i++) { bestV[i] = 3.4e38f; bestI[i] = 0; }

    for (int cc = 0; cc < 8; ++cc) {
        int cBase = cc * 128;
        ull acc[8][4];
#pragma unroll
        for (int i = 0; i < 8; i++)
#pragma unroll
            for (int j = 0; j < 4; j++) acc[i][j] = 0ull;

        for (int kt = 0; kt < 16; ++kt) {
            __syncthreads();
            // fill A (normalized h): 2048 floats; each thread 2 float4
#pragma unroll
            for (int q = 0; q < 2; q++) {
                int t2 = tid * 2 + q;           // 0..511
                int r = t2 >> 2, cg = t2 & 3;
                const float4 v = *(const float4*)(h + (rowBase + r) * DDIM + kt * 16 + cg * 4);
                float s = rsS[r];
                As[cg * 4 + 0][r] = v.x * s;
                As[cg * 4 + 1][r] = v.y * s;
                As[cg * 4 + 2][r] = v.z * s;
                As[cg * 4 + 3][r] = v.w * s;
            }
            // fill B (normalized codes)
#pragma unroll
            for (int q = 0; q < 2; q++) {
                int t2 = tid * 2 + q;
                int c = t2 >> 2, cg = t2 & 3;
                const float4 v = *(const float4*)(g_embedn + (size_t)(cBase + c) * DDIM + kt * 16 + cg * 4);
                Bs[cg * 4 + 0][c] = v.x; Bs[cg * 4 + 1][c] = v.y;
                Bs[cg * 4 + 2][c] = v.z; Bs[cg * 4 + 3][c] = v.w;
            }
            __syncthreads();
#pragma unroll
            for (int kk = 0; kk < 16; kk++) {
                // 8 row values via 2 broadcast LDS.128, duplicate in registers
                const float4* ap = (const float4*)&As[kk][ty * 8];
                float4 av0 = ap[0], av1 = ap[1];
                ull a2[8];
                a2[0] = dup2(av0.x); a2[1] = dup2(av0.y);
                a2[2] = dup2(av0.z); a2[3] = dup2(av0.w);
                a2[4] = dup2(av1.x); a2[5] = dup2(av1.y);
                a2[6] = dup2(av1.z); a2[7] = dup2(av1.w);
                const ull* bp = (const ull*)&Bs[kk][0];
                ull b2[4];
#pragma unroll
                for (int j = 0; j < 4; j++) b2[j] = bp[tx + 16 * j];  // conflict-free LDS.64
#pragma unroll
                for (int i = 0; i < 8; i++)
#pragma unroll
                    for (int j = 0; j < 4; j++) fma2(acc[i][j], a2[i], b2[j]);
            }
        }
        // fold chunk into running argmin (ascending code order => first-min tie-break)
#pragma unroll
        for (int i = 0; i < 8; i++) {
#pragma unroll
            for (int j = 0; j < 4; j++) {
                float2 dv = unpack2(acc[i][j]);
                int c0 = cBase + 2 * tx + 32 * j;
                float d0 = 1.0f - dv.x;
                if (d0 < bestV[i]) { bestV[i] = d0; bestI[i] = c0; }
                float d1 = 1.0f - dv.y;
                if (d1 < bestV[i]) { bestV[i] = d1; bestI[i] = c0 + 1; }
            }
        }
    }

    __syncthreads();
#pragma unroll
    for (int i = 0; i < 8; i++) {
        int r = ty * 8 + i;
        redV[r * 16 + tx] = bestV[i];
        redI[r * 16 + tx] = bestI[i];
    }
    __syncthreads();
    if (tid < 128) {
        float bv = redV[tid * 16]; int bi = redI[tid * 16];
#pragma unroll
        for (int t = 1; t < 16; t++) {
            float v = redV[tid * 16 + t]; int ix = redI[tid * 16 + t];
            if (v < bv || (v == bv && ix < bi)) { bv = v; bi = ix; }
        }
        g_zid[rowBase + tid] = bi;
        out[OFF_ZID + rowBase + tid] = (float)bi;
    }
}

// per-row: z_q gather, z_q_st, commit-loss partials, counts, embed_sum scatter.
// NOTE: out+OFF_ZQ is only 4-byte aligned (odd float offset) -> scalar stores there.
__global__ __launch_bounds__(256) void k_assign(const float* __restrict__ h,
                                                const float* __restrict__ embed,
                                                float* __restrict__ out) {
    __shared__ float wsum[8];
    int lane = threadIdx.x & 31, w = threadIdx.x >> 5;
    size_t row = (size_t)blockIdx.x * 8 + w;
    int code = g_zid[row];
    const float4* hr = (const float4*)(h + row * DDIM);
    const float4* er = (const float4*)(embed + (size_t)code * DDIM);
    float*  zq   = out + OFF_ZQ + row * DDIM;            // 4B-aligned only
    float4* zqst = (float4*)(out + OFF_ZQST + row * DDIM);
    float acc = 0.0f;
#pragma unroll
    for (int t = 0; t < 2; t++) {
        int d4 = lane + 32 * t;
        float4 hv = hr[d4], ev = er[d4];
        zq[d4 * 4 + 0] = ev.x; zq[d4 * 4 + 1] = ev.y;
        zq[d4 * 4 + 2] = ev.z; zq[d4 * 4 + 3] = ev.w;
        float4 st;
        st.x = hv.x + (ev.x - hv.x); st.y = hv.y + (ev.y - hv.y);
        st.z = hv.z + (ev.z - hv.z); st.w = hv.w + (ev.w - hv.w);
        zqst[d4] = st;
        float dx = hv.x - ev.x, dy = hv.y - ev.y, dz = hv.z - ev.z, dw = hv.w - ev.w;
        acc += dx * dx + dy * dy + dz * dz + dw * dw;
        float* es = &g_esum[(size_t)code * DDIM + d4 * 4];
        atomicAdd(es + 0, hv.x); atomicAdd(es + 1, hv.y);
        atomicAdd(es + 2, hv.z); atomicAdd(es + 3, hv.w);
    }
#pragma unroll
    for (int o = 16; o; o >>= 1) acc += __shfl_xor_sync(0xFFFFFFFFu, acc, o);
    if (lane == 0) {
        wsum[w] = acc;
        atomicAdd(&g_counts[code], 1.0f);
    }
    __syncthreads();
    if (threadIdx.x == 0) {
        double s = 0.0;
#pragma unroll
        for (int i = 0; i < 8; i++) s += (double)wsum[i];
        g_losspart[blockIdx.x] = s;
    }
}

// per-code scalars: EMA counts, smoothing, dead detection + threefry revival idx,
// loss, entropy/perplexity. Single block of 1024 threads.
__global__ void k_final_a(const float* __restrict__ cs_in, float* __restrict__ out) {
    __shared__ double sd[1024];
    int t = threadIdx.x;
    float c = g_counts[t];
    float ncs = cs_in[t] * DECAYC + c * (1.0f - DECAYC);

    // n = sum(new_cs)
    sd[t] = (double)ncs; __syncthreads();
    for (int o = 512; o; o >>= 1) { if (t < o) sd[t] += sd[t + o]; __syncthreads(); }
    double n = sd[0]; __syncthreads();

    // entropy
    float usage = c / 131072.0f;
    float term = (usage > 0.0f) ? usage * logf(usage) : 0.0f;
    sd[t] = (double)term; __syncthreads();
    for (int o = 512; o; o >>= 1) { if (t < o) sd[t] += sd[t + o]; __syncthreads(); }
    float ent = -(float)sd[0]; __syncthreads();

    // commit loss
    double lp = 0.0;
    for (int i = t; i < 16384; i += 1024) lp += g_losspart[i];
    sd[t] = lp; __syncthreads();
    for (int o = 512; o; o >>= 1) { if (t < o) sd[t] += sd[t + o]; __syncthreads(); }
    double loss_sum = sd[0];

    float nf = (float)n;
    float meanv = (float)(n / 1024.0);
    float cs_sm = (ncs + EPSC) / (nf + 1024.0f * EPSC) * nf;
    float den = fmaxf(cs_sm, EPSC);
    bool dead = (ncs / (131072.0f + EPSC)) < 0.01f;

    g_den[t] = den;
    g_src[t] = dead ? (int)jax_randint_idx(t) : -1;
    out[OFF_NCS + t] = dead ? fmaxf(meanv, 1.0f) : ncs;

    if (t == 0) {
        out[OFF_LOSS] = (float)(loss_sum / (double)((size_t)NROWS * DDIM)); // COMMIT_W=1
        out[OFF_PPL]  = expf(ent);
    }
}

// per-code rows: new_ea, new_embed (with revival gather)
__global__ void k_final_b(const float* __restrict__ h, const float* __restrict__ ea_in,
                          float* __restrict__ out) {
    int k = blockIdx.x;          // 1024 blocks
    int d = threadIdx.x;         // 256 threads
    size_t idx = (size_t)k * DDIM + d;
    float nea = ea_in[idx] * DECAYC + g_esum[idx] * (1.0f - DECAYC);
    out[OFF_NEA + idx] = nea;
    int src = g_src[k];
    float ne = (src >= 0) ? h[(size_t)src * DDIM + d] : nea / g_den[k];
    out[OFF_NEMB + idx] = ne;
}

// ---------------- launch ----------------
extern "C" void kernel_launch(void* const* d_in, const int* in_sizes, int n_in,
                              void* d_out, int out_size) {
    const float* h     = (const float*)d_in[0];
    const float* embed = (const float*)d_in[1];
    const float* cs    = (const float*)d_in[2];
    const float* ea    = (const float*)d_in[3];
    float* out = (float*)d_out;

    k_zero<<<1024, 256>>>();
    k_norm_embed<<<128, 256>>>(embed);     // 1024 warps
    k_norm_h<<<16384, 256>>>(h);           // 131072 warps
    k_argmin<<<1024, 256>>>(h, out);       // 128 rows/block
    k_assign<<<16384, 256>>>(h, embed, out);
    k_final_a<<<1, 1024>>>(cs, out);
    k_final_b<<<1024, 256>>>(h, ea, out);
}

// round 7
// speedup vs baseline: 1.1913x; 1.0263x over previous
#include <cuda_runtime.h>
#include <math.h>

// ---------------- problem constants ----------------
#define NROWS   131072
#define DDIM    256
#define NCODES  1024
#define EPSC    1e-5f
#define DECAYC  0.99f

typedef unsigned long long ull;

// ---------------- output layout (float32, reference tuple order, flattened) ----------------
#define OFF_ZQST 0ULL
#define OFF_ZID  33554432ULL
#define OFF_LOSS 33685504ULL
#define OFF_ZQ   33685505ULL
#define OFF_NEMB 67239937ULL
#define OFF_NCS  67502081ULL
#define OFF_NEA  67503105ULL
#define OFF_PPL  67765249ULL

// ---------------- device scratch (static: no allocation allowed) ----------------
static __device__ float  g_embedn[NCODES * DDIM];   // normalized codebook
static __device__ float  g_rs[NROWS];               // per-row rsqrt(||h||^2)
static __device__ int    g_zid[NROWS];
static __device__ float  g_counts[NCODES];
static __device__ float  g_esum[NCODES * DDIM];
static __device__ double g_losspart[16384];
static __device__ float  g_den[NCODES];
static __device__ int    g_src[NCODES];             // revival source row or -1

// ---------------- small helpers ----------------
__device__ __forceinline__ void fma2(ull& d, ull a, ull b) {
    asm("fma.rn.f32x2 %0, %1, %2, %0;" : "+l"(d) : "l"(a), "l"(b));
}
__device__ __forceinline__ ull dup2(float v) {
    ull r; unsigned u = __float_as_uint(v);
    asm("mov.b64 %0, {%1, %1};" : "=l"(r) : "r"(u));
    return r;
}
__device__ __forceinline__ float2 unpack2(ull v) {
    float2 r;
    asm("mov.b64 {%0, %1}, %2;" : "=f"(r.x), "=f"(r.y) : "l"(v));
    return r;
}
__device__ __forceinline__ unsigned rotl32(unsigned x, int r) {
    return (x << r) | (x >> (32 - r));
}

// threefry2x32, FULL 20 rounds (5 groups of 4), canonical injection schedule.
__device__ __forceinline__ void tf2x32(unsigned k0, unsigned k1,
                                       unsigned& x0, unsigned& x1) {
    const unsigned ks2 = 0x1BD11BDAu ^ k0 ^ k1;
#define TF_RND(r) { x0 += x1; x1 = rotl32(x1, (r)); x1 ^= x0; }
    x0 += k0; x1 += k1;
    TF_RND(13) TF_RND(15) TF_RND(26) TF_RND(6)
    x0 += k1;  x1 += ks2 + 1u;
    TF_RND(17) TF_RND(29) TF_RND(16) TF_RND(24)
    x0 += ks2; x1 += k0 + 2u;
    TF_RND(13) TF_RND(15) TF_RND(26) TF_RND(6)
    x0 += k0;  x1 += k1 + 3u;
    TF_RND(17) TF_RND(29) TF_RND(16) TF_RND(24)
    x0 += k1;  x1 += ks2 + 4u;
    TF_RND(13) TF_RND(15) TF_RND(26) TF_RND(6)
    x0 += ks2; x1 += k0 + 5u;
#undef TF_RND
}

// jax.random.randint(key(42), (1024,), 0, 131072)[i]  with
// jax_threefry_partitionable = True (JAX >= 0.5 default):
//   k2 = threefry((0,42), (0,1));  bits_i = xor-fold(threefry(k2, (0,i)));
//   span = 2^17 -> idx = bits & 0x1FFFF.
__device__ unsigned jax_randint_idx(int i) {
    unsigned s0 = 0u, s1 = 1u;
    tf2x32(0u, 42u, s0, s1);
    unsigned x0 = 0u, x1 = (unsigned)i;
    tf2x32(s0, s1, x0, x1);
    return (x0 ^ x1) & 0x1FFFFu;
}

// ---------------- kernels ----------------

__global__ void k_zero() {
    int i = blockIdx.x * blockDim.x + threadIdx.x;   // grid covers 262144
    if (i < NCODES * DDIM) g_esum[i] = 0.0f;
    if (i < NCODES)        g_counts[i] = 0.0f;
}

__global__ void k_norm_embed(const float* __restrict__ e) {
    int w = (blockIdx.x * blockDim.x + threadIdx.x) >> 5;
    int lane = threadIdx.x & 31;
    if (w >= NCODES) return;
    const float* row = e + (size_t)w * DDIM;
    float s = 0.0f;
#pragma unroll
    for (int t = 0; t < DDIM / 32; t++) { float v = row[lane + 32 * t]; s += v * v; }
#pragma unroll
    for (int o = 16; o; o >>= 1) s += __shfl_xor_sync(0xFFFFFFFFu, s, o);
    float rs = (float)(1.0 / sqrt((double)fmaxf(s, 1e-12f)));
#pragma unroll
    for (int t = 0; t < DDIM / 32; t++)
        g_embedn[(size_t)w * DDIM + lane + 32 * t] = row[lane + 32 * t] * rs;
}

__global__ void k_norm_h(const float* __restrict__ h) {
    int w = (blockIdx.x * blockDim.x + threadIdx.x) >> 5;
    int lane = threadIdx.x & 31;
    if (w >= NROWS) return;
    const float4* row = (const float4*)(h + (size_t)w * DDIM);
    float s = 0.0f;
#pragma unroll
    for (int t = 0; t < 2; t++) {
        float4 v = row[lane + 32 * t];
        s += v.x * v.x + v.y * v.y + v.z * v.z + v.w * v.w;
    }
#pragma unroll
    for (int o = 16; o; o >>= 1) s += __shfl_xor_sync(0xFFFFFFFFu, s, o);
    if (lane == 0) g_rs[w] = (float)(1.0 / sqrt((double)fmaxf(s, 1e-12f)));
}

// 128-row x 1024-code argmin GEMM, FP32 via packed f32x2 FMA.
// Double-buffered smem pipeline: prefetch kt+1 (LDG->regs) under compute of kt.
__global__ __launch_bounds__(256, 2) void k_argmin(const float* __restrict__ h,
                                                   float* __restrict__ out) {
    __shared__ __align__(16) float As[2][16][128];   // normalized h rows (k-major)
    __shared__ __align__(16) float Bs[2][16][128];   // normalized codes
    __shared__ float rsS[128];
    __shared__ float redV[128 * 16];
    __shared__ int   redI[128 * 16];

    int tid = threadIdx.x;
    int tx = tid & 15, ty = tid >> 4;
    size_t rowBase = (size_t)blockIdx.x * 128;

    if (tid < 128) rsS[tid] = g_rs[rowBase + tid];
    __syncthreads();

    // per-thread fill coordinates (two float4 each for A and B)
    int t2a = tid * 2,     ra = t2a >> 2, cga = t2a & 3;
    int t2b = tid * 2 + 1, rb = t2b >> 2, cgb = t2b & 3;
    float sa = rsS[ra], sb = rsS[rb];

    float bestV[8]; int bestI[8];
#pragma unroll
    for (int i = 0; i < 8; i++) { bestV[i] = 3.4e38f; bestI[i] = 0; }

    for (int cc = 0; cc < 8; ++cc) {
        int cBase = cc * 128;
        ull acc[8][4];
#pragma unroll
        for (int i = 0; i < 8; i++)
#pragma unroll
            for (int j = 0; j < 4; j++) acc[i][j] = 0ull;

        // prologue: load kt=0 into registers
        float4 vA0 = *(const float4*)(h + (rowBase + ra) * DDIM + cga * 4);
        float4 vA1 = *(const float4*)(h + (rowBase + rb) * DDIM + cgb * 4);
        float4 vB0 = *(const float4*)(g_embedn + (size_t)(cBase + ra) * DDIM + cga * 4);
        float4 vB1 = *(const float4*)(g_embedn + (size_t)(cBase + rb) * DDIM + cgb * 4);

        for (int kt = 0; kt < 16; ++kt) {
            int buf = kt & 1;
            // store prefetched regs into this kt's buffer
            As[buf][cga * 4 + 0][ra] = vA0.x * sa;
            As[buf][cga * 4 + 1][ra] = vA0.y * sa;
            As[buf][cga * 4 + 2][ra] = vA0.z * sa;
            As[buf][cga * 4 + 3][ra] = vA0.w * sa;
            As[buf][cgb * 4 + 0][rb] = vA1.x * sb;
            As[buf][cgb * 4 + 1][rb] = vA1.y * sb;
            As[buf][cgb * 4 + 2][rb] = vA1.z * sb;
            As[buf][cgb * 4 + 3][rb] = vA1.w * sb;
            Bs[buf][cga * 4 + 0][ra] = vB0.x;
            Bs[buf][cga * 4 + 1][ra] = vB0.y;
            Bs[buf][cga * 4 + 2][ra] = vB0.z;
            Bs[buf][cga * 4 + 3][ra] = vB0.w;
            Bs[buf][cgb * 4 + 0][rb] = vB1.x;
            Bs[buf][cgb * 4 + 1][rb] = vB1.y;
            Bs[buf][cgb * 4 + 2][rb] = vB1.z;
            Bs[buf][cgb * 4 + 3][rb] = vB1.w;
            __syncthreads();

            // prefetch kt+1 (hidden under the 16-kk compute below)
            if (kt < 15) {
                int ko = (kt + 1) * 16;
                vA0 = *(const float4*)(h + (rowBase + ra) * DDIM + ko + cga * 4);
                vA1 = *(const float4*)(h + (rowBase + rb) * DDIM + ko + cgb * 4);
                vB0 = *(const float4*)(g_embedn + (size_t)(cBase + ra) * DDIM + ko + cga * 4);
                vB1 = *(const float4*)(g_embedn + (size_t)(cBase + rb) * DDIM + ko + cgb * 4);
            }

#pragma unroll
            for (int kk = 0; kk < 16; kk++) {
                // 8 row values via 2 broadcast LDS.128, duplicate in registers
                const float4* ap = (const float4*)&As[buf][kk][ty * 8];
                float4 av0 = ap[0], av1 = ap[1];
                ull a2[8];
                a2[0] = dup2(av0.x); a2[1] = dup2(av0.y);
                a2[2] = dup2(av0.z); a2[3] = dup2(av0.w);
                a2[4] = dup2(av1.x); a2[5] = dup2(av1.y);
                a2[6] = dup2(av1.z); a2[7] = dup2(av1.w);
                const ull* bp = (const ull*)&Bs[buf][kk][0];
                ull b2[4];
#pragma unroll
                for (int j = 0; j < 4; j++) b2[j] = bp[tx + 16 * j];  // conflict-free LDS.64
#pragma unroll
                for (int i = 0; i < 8; i++)
#pragma unroll
                    for (int j = 0; j < 4; j++) fma2(acc[i][j], a2[i], b2[j]);
            }
        }
        // fold chunk into running argmin (ascending code order => first-min tie-break)
#pragma unroll
        for (int i = 0; i < 8; i++) {
#pragma unroll
            for (int j = 0; j < 4; j++) {
                float2 dv = unpack2(acc[i][j]);
                int c0 = cBase + 2 * tx + 32 * j;
                float d0 = 1.0f - dv.x;
                if (d0 < bestV[i]) { bestV[i] = d0; bestI[i] = c0; }
                float d1 = 1.0f - dv.y;
                if (d1 < bestV[i]) { bestV[i] = d1; bestI[i] = c0 + 1; }
            }
        }
        __syncthreads();   // drain readers of both buffers before next cc overwrites
    }

#pragma unroll
    for (int i = 0; i < 8; i++) {
        int r = ty * 8 + i;
        redV[r * 16 + tx] = bestV[i];
        redI[r * 16 + tx] = bestI[i];
    }
    __syncthreads();
    if (tid < 128) {
        float bv = redV[tid * 16]; int bi = redI[tid * 16];
#pragma unroll
        for (int t = 1; t < 16; t++) {
            float v = redV[tid * 16 + t]; int ix = redI[tid * 16 + t];
            if (v < bv || (v == bv && ix < bi)) { bv = v; bi = ix; }
        }
        g_zid[rowBase + tid] = bi;
        out[OFF_ZID + rowBase + tid] = (float)bi;
    }
}

// per-row: z_q gather, z_q_st, commit-loss partials, counts, embed_sum scatter.
// NOTE: out+OFF_ZQ is only 4-byte aligned (odd float offset) -> scalar stores there.
__global__ __launch_bounds__(256) void k_assign(const float* __restrict__ h,
                                                const float* __restrict__ embed,
                                                float* __restrict__ out) {
    __shared__ float wsum[8];
    int lane = threadIdx.x & 31, w = threadIdx.x >> 5;
    size_t row = (size_t)blockIdx.x * 8 + w;
    int code = g_zid[row];
    const float4* hr = (const float4*)(h + row * DDIM);
    const float4* er = (const float4*)(embed + (size_t)code * DDIM);
    float*  zq   = out + OFF_ZQ + row * DDIM;            // 4B-aligned only
    float4* zqst = (float4*)(out + OFF_ZQST + row * DDIM);
    float acc = 0.0f;
#pragma unroll
    for (int t = 0; t < 2; t++) {
        int d4 = lane + 32 * t;
        float4 hv = hr[d4], ev = er[d4];
        zq[d4 * 4 + 0] = ev.x; zq[d4 * 4 + 1] = ev.y;
        zq[d4 * 4 + 2] = ev.z; zq[d4 * 4 + 3] = ev.w;
        float4 st;
        st.x = hv.x + (ev.x - hv.x); st.y = hv.y + (ev.y - hv.y);
        st.z = hv.z + (ev.z - hv.z); st.w = hv.w + (ev.w - hv.w);
        zqst[d4] = st;
        float dx = hv.x - ev.x, dy = hv.y - ev.y, dz = hv.z - ev.z, dw = hv.w - ev.w;
        acc += dx * dx + dy * dy + dz * dz + dw * dw;
        float* es = &g_esum[(size_t)code * DDIM + d4 * 4];
        atomicAdd(es + 0, hv.x); atomicAdd(es + 1, hv.y);
        atomicAdd(es + 2, hv.z); atomicAdd(es + 3, hv.w);
    }
#pragma unroll
    for (int o = 16; o; o >>= 1) acc += __shfl_xor_sync(0xFFFFFFFFu, acc, o);
    if (lane == 0) {
        wsum[w] = acc;
        atomicAdd(&g_counts[code], 1.0f);
    }
    __syncthreads();
    if (threadIdx.x == 0) {
        double s = 0.0;
#pragma unroll
        for (int i = 0; i < 8; i++) s += (double)wsum[i];
        g_losspart[blockIdx.x] = s;
    }
}

// per-code scalars: EMA counts, smoothing, dead detection + threefry revival idx,
// loss, entropy/perplexity. Single block of 1024 threads.
__global__ void k_final_a(const float* __restrict__ cs_in, float* __restrict__ out) {
    __shared__ double sd[1024];
    int t = threadIdx.x;
    float c = g_counts[t];
    float ncs = cs_in[t] * DECAYC + c * (1.0f - DECAYC);

    // n = sum(new_cs)
    sd[t] = (double)ncs; __syncthreads();
    for (int o = 512; o; o >>= 1) { if (t < o) sd[t] += sd[t + o]; __syncthreads(); }
    double n = sd[0]; __syncthreads();

    // entropy
    float usage = c / 131072.0f;
    float term = (usage > 0.0f) ? usage * logf(usage) : 0.0f;
    sd[t] = (double)term; __syncthreads();
    for (int o = 512; o; o >>= 1) { if (t < o) sd[t] += sd[t + o]; __syncthreads(); }
    float ent = -(float)sd[0]; __syncthreads();

    // commit loss
    double lp = 0.0;
    for (int i = t; i < 16384; i += 1024) lp += g_losspart[i];
    sd[t] = lp; __syncthreads();
    for (int o = 512; o; o >>= 1) { if (t < o) sd[t] += sd[t + o]; __syncthreads(); }
    double loss_sum = sd[0];

    float nf = (float)n;
    float meanv = (float)(n / 1024.0);
    float cs_sm = (ncs + EPSC) / (nf + 1024.0f * EPSC) * nf;
    float den = fmaxf(cs_sm, EPSC);
    bool dead = (ncs / (131072.0f + EPSC)) < 0.01f;

    g_den[t] = den;
    g_src[t] = dead ? (int)jax_randint_idx(t) : -1;
    out[OFF_NCS + t] = dead ? fmaxf(meanv, 1.0f) : ncs;

    if (t == 0) {
        out[OFF_LOSS] = (float)(loss_sum / (double)((size_t)NROWS * DDIM)); // COMMIT_W=1
        out[OFF_PPL]  = expf(ent);
    }
}

// per-code rows: new_ea, new_embed (with revival gather)
__global__ void k_final_b(const float* __restrict__ h, const float* __restrict__ ea_in,
                          float* __restrict__ out) {
    int k = blockIdx.x;          // 1024 blocks
    int d = threadIdx.x;         // 256 threads
    size_t idx = (size_t)k * DDIM + d;
    float nea = ea_in[idx] * DECAYC + g_esum[idx] * (1.0f - DECAYC);
    out[OFF_NEA + idx] = nea;
    int src = g_src[k];
    float ne = (src >= 0) ? h[(size_t)src * DDIM + d] : nea / g_den[k];
    out[OFF_NEMB + idx] = ne;
}

// ---------------- launch ----------------
extern "C" void kernel_launch(void* const* d_in, const int* in_sizes, int n_in,
                              void* d_out, int out_size) {
    const float* h     = (const float*)d_in[0];
    const float* embed = (const float*)d_in[1];
    const float* cs    = (const float*)d_in[2];
    const float* ea    = (const float*)d_in[3];
    float* out = (float*)d_out;

    k_zero<<<1024, 256>>>();
    k_norm_embed<<<128, 256>>>(embed);     // 1024 warps
    k_norm_h<<<16384, 256>>>(h);           // 131072 warps
    k_argmin<<<1024, 256>>>(h, out);       // 128 rows/block
    k_assign<<<16384, 256>>>(h, embed, out);
    k_final_a<<<1, 1024>>>(cs, out);
    k_final_b<<<1024, 256>>>(h, ea, out);
}

// round 9
// speedup vs baseline: 1.6972x; 1.4247x over previous
#include <cuda_runtime.h>
#include <cuda_bf16.h>
#include <math.h>
#include <stdint.h>

// ---------------- problem constants ----------------
#define NROWS   131072
#define DDIM    256
#define NCODES  1024
#define EPSC    1e-5f
#define DECAYC  0.99f

// ---------------- output layout (float32, reference tuple order, flattened) ----------------
#define OFF_ZQST 0ULL
#define OFF_ZID  33554432ULL
#define OFF_LOSS 33685504ULL
#define OFF_ZQ   33685505ULL
#define OFF_NEMB 67239937ULL
#define OFF_NCS  67502081ULL
#define OFF_NEA  67503105ULL
#define OFF_PPL  67765249ULL

// ---------------- device scratch (static: no allocation allowed) ----------------
static __device__ __nv_bfloat16 g_hb0[NROWS * DDIM];   // normalized h, bf16 hi
static __device__ __nv_bfloat16 g_hb1[NROWS * DDIM];   // mid
static __device__ __nv_bfloat16 g_hb2[NROWS * DDIM];   // lo
static __device__ __nv_bfloat16 g_eb0[NCODES * DDIM];  // normalized embed splits
static __device__ __nv_bfloat16 g_eb1[NCODES * DDIM];
static __device__ __nv_bfloat16 g_eb2[NCODES * DDIM];
static __device__ int    g_zid[NROWS];
static __device__ float  g_counts[NCODES];
static __device__ float  g_esum[NCODES * DDIM];
static __device__ double g_losspart[16384];
static __device__ float  g_den[NCODES];
static __device__ int    g_src[NCODES];

// ---------------- PTX helpers (baseline sm_80+ features only) ----------------
__device__ __forceinline__ uint32_t smem_u32(const void* p) {
    uint32_t a;
    asm("{ .reg .u64 t; cvta.to.shared.u64 t, %1; cvt.u32.u64 %0, t; }" : "=r"(a) : "l"(p));
    return a;
}
__device__ __forceinline__ void cpa16(uint32_t dst, const void* src) {
    asm volatile("cp.async.cg.shared.global [%0], [%1], 16;" :: "r"(dst), "l"(src) : "memory");
}
#define CP_COMMIT() asm volatile("cp.async.commit_group;" ::: "memory")
#define CP_WAIT0()  asm volatile("cp.async.wait_group 0;" ::: "memory")

__device__ __forceinline__ void ldmx4(uint32_t* r, uint32_t addr) {
    asm volatile("ldmatrix.sync.aligned.m8n8.x4.shared.b16 {%0,%1,%2,%3}, [%4];"
        : "=r"(r[0]), "=r"(r[1]), "=r"(r[2]), "=r"(r[3]) : "r"(addr));
}
__device__ __forceinline__ void hmma(float* c, const uint32_t* a, const uint32_t* b) {
    asm volatile("mma.sync.aligned.m16n8k16.row.col.f32.bf16.bf16.f32 "
        "{%0,%1,%2,%3}, {%4,%5,%6,%7}, {%8,%9}, {%0,%1,%2,%3};"
        : "+f"(c[0]), "+f"(c[1]), "+f"(c[2]), "+f"(c[3])
        : "r"(a[0]), "r"(a[1]), "r"(a[2]), "r"(a[3]), "r"(b[0]), "r"(b[1]));
}
// 16B-granule XOR swizzle within 128B rows (conflict-free ldmatrix)
__device__ __forceinline__ uint32_t swzoff(int r, int ci) {
    uint32_t o = (uint32_t)(r * 128 + ci * 16);
    return o ^ ((o >> 3) & 0x70);
}

// ---------------- threefry / jax randint ----------------
__device__ __forceinline__ unsigned rotl32(unsigned x, int r) { return (x << r) | (x >> (32 - r)); }
__device__ __forceinline__ void tf2x32(unsigned k0, unsigned k1, unsigned& x0, unsigned& x1) {
    const unsigned ks2 = 0x1BD11BDAu ^ k0 ^ k1;
#define TF_RND(r) { x0 += x1; x1 = rotl32(x1, (r)); x1 ^= x0; }
    x0 += k0; x1 += k1;
    TF_RND(13) TF_RND(15) TF_RND(26) TF_RND(6)
    x0 += k1;  x1 += ks2 + 1u;
    TF_RND(17) TF_RND(29) TF_RND(16) TF_RND(24)
    x0 += ks2; x1 += k0 + 2u;
    TF_RND(13) TF_RND(15) TF_RND(26) TF_RND(6)
    x0 += k0;  x1 += k1 + 3u;
    TF_RND(17) TF_RND(29) TF_RND(16) TF_RND(24)
    x0 += k1;  x1 += ks2 + 4u;
    TF_RND(13) TF_RND(15) TF_RND(26) TF_RND(6)
    x0 += ks2; x1 += k0 + 5u;
#undef TF_RND
}
__device__ unsigned jax_randint_idx(int i) {
    unsigned s0 = 0u, s1 = 1u;
    tf2x32(0u, 42u, s0, s1);
    unsigned x0 = 0u, x1 = (unsigned)i;
    tf2x32(s0, s1, x0, x1);
    return (x0 ^ x1) & 0x1FFFFu;
}

// ---------------- bf16 triple split ----------------
__device__ __forceinline__ void bsplit(float a, unsigned& u0, unsigned& u1, unsigned& u2) {
    __nv_bfloat16 b0 = __float2bfloat16_rn(a);
    float f0 = __bfloat162float(b0);
    float r = a - f0;
    __nv_bfloat16 b1 = __float2bfloat16_rn(r);
    float f1 = __bfloat162float(b1);
    __nv_bfloat16 b2 = __float2bfloat16_rn(r - f1);
    u0 = (unsigned)__bfloat16_as_ushort(b0);
    u1 = (unsigned)__bfloat16_as_ushort(b1);
    u2 = (unsigned)__bfloat16_as_ushort(b2);
}

// ---------------- simple kernels ----------------
__global__ void k_zero() {
    int i = blockIdx.x * blockDim.x + threadIdx.x;
    if (i < NCODES * DDIM) g_esum[i] = 0.0f;
    if (i < NCODES)        g_counts[i] = 0.0f;
}

// normalize h rows and write 3-way bf16 splits (warp per row)
__global__ void k_prep_h(const float* __restrict__ h) {
    int w = (blockIdx.x * blockDim.x + threadIdx.x) >> 5;
    int lane = threadIdx.x & 31;
    if (w >= NROWS) return;
    const float4* row = (const float4*)(h + (size_t)w * DDIM);
    float4 v[2];
    float s = 0.0f;
#pragma unroll
    for (int t = 0; t < 2; t++) {
        v[t] = row[lane + 32 * t];
        s += v[t].x * v[t].x + v[t].y * v[t].y + v[t].z * v[t].z + v[t].w * v[t].w;
    }
#pragma unroll
    for (int o = 16; o; o >>= 1) s += __shfl_xor_sync(0xFFFFFFFFu, s, o);
    float rs = (float)(1.0 / sqrt((double)fmaxf(s, 1e-12f)));
#pragma unroll
    for (int t = 0; t < 2; t++) {
        int f = lane + 32 * t;
        float a[4] = { v[t].x * rs, v[t].y * rs, v[t].z * rs, v[t].w * rs };
        unsigned u0[4], u1[4], u2[4];
#pragma unroll
        for (int e = 0; e < 4; e++) bsplit(a[e], u0[e], u1[e], u2[e]);
        size_t off = (size_t)w * DDIM + f * 4;
        *(uint2*)(g_hb0 + off) = make_uint2(u0[0] | (u0[1] << 16), u0[2] | (u0[3] << 16));
        *(uint2*)(g_hb1 + off) = make_uint2(u1[0] | (u1[1] << 16), u1[2] | (u1[3] << 16));
        *(uint2*)(g_hb2 + off) = make_uint2(u2[0] | (u2[1] << 16), u2[2] | (u2[3] << 16));
    }
}

// normalize embed rows and write 3-way bf16 splits
__global__ void k_prep_embed(const float* __restrict__ e) {
    int w = (blockIdx.x * blockDim.x + threadIdx.x) >> 5;
    int lane = threadIdx.x & 31;
    if (w >= NCODES) return;
    const float* row = e + (size_t)w * DDIM;
    float s = 0.0f;
#pragma unroll
    for (int t = 0; t < 8; t++) { float v = row[lane + 32 * t]; s += v * v; }
#pragma unroll
    for (int o = 16; o; o >>= 1) s += __shfl_xor_sync(0xFFFFFFFFu, s, o);
    float rs = (float)(1.0 / sqrt((double)fmaxf(s, 1e-12f)));
#pragma unroll
    for (int t = 0; t < 8; t++) {
        int d = lane + 32 * t;
        float a = row[d] * rs;
        unsigned u0, u1, u2;
        bsplit(a, u0, u1, u2);
        size_t idx = (size_t)w * DDIM + d;
        g_eb0[idx] = __ushort_as_bfloat16((unsigned short)u0);
        g_eb1[idx] = __ushort_as_bfloat16((unsigned short)u1);
        g_eb2[idx] = __ushort_as_bfloat16((unsigned short)u2);
    }
}

// ---------------- HMMA argmin GEMM ----------------
// buffer: A splits (3 x 16KB) then B splits (3 x 16KB); double buffered.
#define BUF_BYTES 98304u
#define SMEM_DYN  (2u * BUF_BYTES + 2048u)

__device__ __forceinline__ void issue_loads(int tid, size_t rowBase, int s2, uint32_t buf) {
    const int cc = s2 >> 2, kt = s2 & 3;
    const __nv_bfloat16* hb[3] = { g_hb0, g_hb1, g_hb2 };
    const __nv_bfloat16* eb[3] = { g_eb0, g_eb1, g_eb2 };
#pragma unroll
    for (int t = 0; t < 3; t++) {
#pragma unroll
        for (int q = 0; q < 4; q++) {
            int idx = tid + 256 * q;           // 1024 granules of 16B per split
            int r = idx >> 3, ci = idx & 7;
            uint32_t sw = swzoff(r, ci);
            cpa16(buf + t * 16384u + sw,
                  hb[t] + (rowBase + r) * DDIM + kt * 64 + ci * 8);
            cpa16(buf + 49152u + t * 16384u + sw,
                  eb[t] + (size_t)(cc * 128 + r) * DDIM + kt * 64 + ci * 8);
        }
    }
}

__global__ __launch_bounds__(256, 1) void k_argmin_mma(float* __restrict__ out) {
    extern __shared__ __align__(1024) char smem[];
    const uint32_t sb = smem_u32(smem);
    const int tid = threadIdx.x, lane = tid & 31, w = tid >> 5;
    const size_t rowBase = (size_t)blockIdx.x * 128;

    const int mbase = (w & 3) * 32;    // warp's 32 rows within 128
    const int nbw   = (w >> 2) * 64;   // warp's 64 codes within 128-chunk

    float acc[2][8][4];
    float bestV[4]; int bestI[4];
#pragma unroll
    for (int b = 0; b < 4; b++) { bestV[b] = 3.4e38f; bestI[b] = 0; }

    // ldmatrix lane address components
    const int arow = mbase + (lane & 7) + ((lane >> 3) & 1) * 8;
    const int aciX = (lane >> 4);
    const int brow = nbw + (lane & 7) + ((lane >> 4) << 3);
    const int bciX = ((lane >> 3) & 1);

    issue_loads(tid, rowBase, 0, sb);
    CP_COMMIT(); CP_WAIT0(); __syncthreads();

    for (int s = 0; s < 32; s++) {              // s = cc*4 + kt
        const uint32_t buf = sb + (uint32_t)(s & 1) * BUF_BYTES;
        if ((s & 3) == 0) {
#pragma unroll
            for (int mi = 0; mi < 2; mi++)
#pragma unroll
                for (int nj = 0; nj < 8; nj++)
#pragma unroll
                    for (int rr = 0; rr < 4; rr++) acc[mi][nj][rr] = 0.0f;
        }
        if (s < 31) {
            issue_loads(tid, rowBase, s + 1, sb + (uint32_t)((s + 1) & 1) * BUF_BYTES);
            CP_COMMIT();
        }

#pragma unroll
        for (int ks = 0; ks < 4; ks++) {
            uint32_t Aoff = swzoff(arow, ks * 2 + aciX);
            uint32_t A[3][2][4];
#pragma unroll
            for (int t = 0; t < 3; t++) {
                ldmx4(A[t][0], buf + t * 16384u + Aoff);
                ldmx4(A[t][1], buf + t * 16384u + Aoff + 2048u);
            }
            uint32_t Boff = swzoff(brow, ks * 2 + bciX);
#pragma unroll
            for (int bj = 0; bj < 3; bj++) {
                uint32_t Bf[4][4];
#pragma unroll
                for (int p = 0; p < 4; p++)
                    ldmx4(Bf[p], buf + 49152u + bj * 16384u + Boff + p * 2048u);
                const int na = (bj == 0) ? 3 : ((bj == 1) ? 2 : 1);
#pragma unroll
                for (int ai = 0; ai < 3; ai++) {
                    if (ai >= na) break;
#pragma unroll
                    for (int p = 0; p < 4; p++)
#pragma unroll
                        for (int mi = 0; mi < 2; mi++) {
                            hmma(acc[mi][2 * p],     A[ai][mi], &Bf[p][0]);
                            hmma(acc[mi][2 * p + 1], A[ai][mi], &Bf[p][2]);
                        }
                }
            }
        }

        if ((s & 3) == 3) {                 // chunk done: fold argmin
            const int cc = s >> 2;
#pragma unroll
            for (int mi = 0; mi < 2; mi++)
#pragma unroll
                for (int nj = 0; nj < 8; nj++) {
                    int col0 = cc * 128 + nbw + nj * 8 + (lane & 3) * 2;
                    float d0 = 1.0f - acc[mi][nj][0];
                    float d1 = 1.0f - acc[mi][nj][1];
                    float d2 = 1.0f - acc[mi][nj][2];
                    float d3 = 1.0f - acc[mi][nj][3];
                    int b0 = 2 * mi, b1 = 2 * mi + 1;
                    if (d0 < bestV[b0]) { bestV[b0] = d0; bestI[b0] = col0; }
                    if (d1 < bestV[b0]) { bestV[b0] = d1; bestI[b0] = col0 + 1; }
                    if (d2 < bestV[b1]) { bestV[b1] = d2; bestI[b1] = col0; }
                    if (d3 < bestV[b1]) { bestV[b1] = d3; bestI[b1] = col0 + 1; }
                }
        }

        if (s < 31) { CP_WAIT0(); __syncthreads(); }
    }

    // quad reduce: lanes 4q..4q+3 share the same 4 rows; prefer lower lane (lower col) on ties via index compare
#pragma unroll
    for (int off = 1; off <= 2; off <<= 1) {
#pragma unroll
        for (int b = 0; b < 4; b++) {
            float v = __shfl_down_sync(0xFFFFFFFFu, bestV[b], off);
            int   i = __shfl_down_sync(0xFFFFFFFFu, bestI[b], off);
            if (v < bestV[b] || (v == bestV[b] && i < bestI[b])) { bestV[b] = v; bestI[b] = i; }
        }
    }
    float* redV = (float*)(smem + 2 * BUF_BYTES);
    int*   redI = (int*)(smem + 2 * BUF_BYTES + 1024);
    if ((lane & 3) == 0) {
#pragma unroll
        for (int b = 0; b < 4; b++) {
            int row = mbase + (b >> 1) * 16 + (lane >> 2) + (b & 1) * 8;
            int half = w >> 2;
            redV[row * 2 + half] = bestV[b];
            redI[row * 2 + half] = bestI[b];
        }
    }
    __syncthreads();
    if (tid < 128) {
        float v0 = redV[tid * 2], v1 = redV[tid * 2 + 1];
        int i0 = redI[tid * 2], i1 = redI[tid * 2 + 1];
        int bi = (v1 < v0 || (v1 == v0 && i1 < i0)) ? i1 : i0;
        g_zid[rowBase + tid] = bi;
        out[OFF_ZID + rowBase + tid] = (float)bi;
    }
}

// ---------------- per-row assign / scatter ----------------
__global__ __launch_bounds__(256) void k_assign(const float* __restrict__ h,
                                                const float* __restrict__ embed,
                                                float* __restrict__ out) {
    __shared__ float wsum[8];
    int lane = threadIdx.x & 31, w = threadIdx.x >> 5;
    size_t row = (size_t)blockIdx.x * 8 + w;
    int code = g_zid[row];
    const float4* hr = (const float4*)(h + row * DDIM);
    const float4* er = (const float4*)(embed + (size_t)code * DDIM);
    float*  zq   = out + OFF_ZQ + row * DDIM;            // 4B-aligned only
    float4* zqst = (float4*)(out + OFF_ZQST + row * DDIM);
    float acc = 0.0f;
#pragma unroll
    for (int t = 0; t < 2; t++) {
        int d4 = lane + 32 * t;
        float4 hv = hr[d4], ev = er[d4];
        zq[d4 * 4 + 0] = ev.x; zq[d4 * 4 + 1] = ev.y;
        zq[d4 * 4 + 2] = ev.z; zq[d4 * 4 + 3] = ev.w;
        float4 st;
        st.x = hv.x + (ev.x - hv.x); st.y = hv.y + (ev.y - hv.y);
        st.z = hv.z + (ev.z - hv.z); st.w = hv.w + (ev.w - hv.w);
        zqst[d4] = st;
        float dx = hv.x - ev.x, dy = hv.y - ev.y, dz = hv.z - ev.z, dw = hv.w - ev.w;
        acc += dx * dx + dy * dy + dz * dz + dw * dw;
        float* es = &g_esum[(size_t)code * DDIM + d4 * 4];
        atomicAdd(es + 0, hv.x); atomicAdd(es + 1, hv.y);
        atomicAdd(es + 2, hv.z); atomicAdd(es + 3, hv.w);
    }
#pragma unroll
    for (int o = 16; o; o >>= 1) acc += __shfl_xor_sync(0xFFFFFFFFu, acc, o);
    if (lane == 0) {
        wsum[w] = acc;
        atomicAdd(&g_counts[code], 1.0f);
    }
    __syncthreads();
    if (threadIdx.x == 0) {
        double sum = 0.0;
#pragma unroll
        for (int i = 0; i < 8; i++) sum += (double)wsum[i];
        g_losspart[blockIdx.x] = sum;
    }
}

// ---------------- per-code scalars ----------------
__global__ void k_final_a(const float* __restrict__ cs_in, float* __restrict__ out) {
    __shared__ double sd[1024];
    int t = threadIdx.x;
    float c = g_counts[t];
    float ncs = cs_in[t] * DECAYC + c * (1.0f - DECAYC);

    sd[t] = (double)ncs; __syncthreads();
    for (int o = 512; o; o >>= 1) { if (t < o) sd[t] += sd[t + o]; __syncthreads(); }
    double n = sd[0]; __syncthreads();

    float usage = c / 131072.0f;
    float term = (usage > 0.0f) ? usage * logf(usage) : 0.0f;
    sd[t] = (double)term; __syncthreads();
    for (int o = 512; o; o >>= 1) { if (t < o) sd[t] += sd[t + o]; __syncthreads(); }
    float ent = -(float)sd[0]; __syncthreads();

    double lp = 0.0;
    for (int i = t; i < 16384; i += 1024) lp += g_losspart[i];
    sd[t] = lp; __syncthreads();
    for (int o = 512; o; o >>= 1) { if (t < o) sd[t] += sd[t + o]; __syncthreads(); }
    double loss_sum = sd[0];

    float nf = (float)n;
    float meanv = (float)(n / 1024.0);
    float cs_sm = (ncs + EPSC) / (nf + 1024.0f * EPSC) * nf;
    float den = fmaxf(cs_sm, EPSC);
    bool dead = (ncs / (131072.0f + EPSC)) < 0.01f;

    g_den[t] = den;
    g_src[t] = dead ? (int)jax_randint_idx(t) : -1;
    out[OFF_NCS + t] = dead ? fmaxf(meanv, 1.0f) : ncs;

    if (t == 0) {
        out[OFF_LOSS] = (float)(loss_sum / (double)((size_t)NROWS * DDIM));
        out[OFF_PPL]  = expf(ent);
    }
}

__global__ void k_final_b(const float* __restrict__ h, const float* __restrict__ ea_in,
                          float* __restrict__ out) {
    int k = blockIdx.x;
    int d = threadIdx.x;
    size_t idx = (size_t)k * DDIM + d;
    float nea = ea_in[idx] * DECAYC + g_esum[idx] * (1.0f - DECAYC);
    out[OFF_NEA + idx] = nea;
    int src = g_src[k];
    float ne = (src >= 0) ? h[(size_t)src * DDIM + d] : nea / g_den[k];
    out[OFF_NEMB + idx] = ne;
}

// ---------------- launch ----------------
extern "C" void kernel_launch(void* const* d_in, const int* in_sizes, int n_in,
                              void* d_out, int out_size) {
    const float* h     = (const float*)d_in[0];
    const float* embed = (const float*)d_in[1];
    const float* cs    = (const float*)d_in[2];
    const float* ea    = (const float*)d_in[3];
    float* out = (float*)d_out;

    static int smem_set = 0;
    if (!smem_set) {
        cudaFuncSetAttribute(k_argmin_mma, cudaFuncAttributeMaxDynamicSharedMemorySize, SMEM_DYN);
        smem_set = 1;
    }

    k_zero<<<1024, 256>>>();
    k_prep_h<<<16384, 256>>>(h);
    k_prep_embed<<<128, 256>>>(embed);
    k_argmin_mma<<<1024, 256, SMEM_DYN>>>(out);
    k_assign<<<16384, 256>>>(h, embed, out);
    k_final_a<<<1, 1024>>>(cs, out);
    k_final_b<<<1024, 256>>>(h, ea, out);
}

// round 10
// speedup vs baseline: 2.4973x; 1.4714x over previous
#include <cuda_runtime.h>
#include <cuda_fp16.h>
#include <math.h>
#include <stdint.h>

// ---------------- problem constants ----------------
#define NROWS   131072
#define DDIM    256
#define NCODES  1024
#define EPSC    1e-5f
#define DECAYC  0.99f

// ---------------- output layout (float32, reference tuple order, flattened) ----------------
#define OFF_ZQST 0ULL
#define OFF_ZID  33554432ULL
#define OFF_LOSS 33685504ULL
#define OFF_ZQ   33685505ULL
#define OFF_NEMB 67239937ULL
#define OFF_NCS  67502081ULL
#define OFF_NEA  67503105ULL
#define OFF_PPL  67765249ULL

#define CORR_SCALE 1024.0f
#define CORR_INV   0.0009765625f   // 2^-10

// ---------------- device scratch (static: no allocation allowed) ----------------
static __device__ __half g_h0[NROWS * DDIM];    // fp16(normalized h)
static __device__ __half g_h1[NROWS * DDIM];    // fp16((hn - h0) * 2^10)
static __device__ __half g_e0[NCODES * DDIM];   // fp16(normalized embed)
static __device__ __half g_e1[NCODES * DDIM];   // fp16((en - e0) * 2^10)
static __device__ int    g_zid[NROWS];
static __device__ float  g_counts[NCODES];
static __device__ float  g_esum[NCODES * DDIM];
static __device__ double g_losspart[16384];
static __device__ float  g_den[NCODES];
static __device__ int    g_src[NCODES];

// ---------------- PTX helpers (baseline sm_80+ features only) ----------------
__device__ __forceinline__ uint32_t smem_u32(const void* p) {
    uint32_t a;
    asm("{ .reg .u64 t; cvta.to.shared.u64 t, %1; cvt.u32.u64 %0, t; }" : "=r"(a) : "l"(p));
    return a;
}
__device__ __forceinline__ void cpa16(uint32_t dst, const void* src) {
    asm volatile("cp.async.cg.shared.global [%0], [%1], 16;" :: "r"(dst), "l"(src) : "memory");
}
#define CP_COMMIT() asm volatile("cp.async.commit_group;" ::: "memory")
#define CP_WAIT0()  asm volatile("cp.async.wait_group 0;" ::: "memory")

__device__ __forceinline__ void ldmx4(uint32_t* r, uint32_t addr) {
    asm volatile("ldmatrix.sync.aligned.m8n8.x4.shared.b16 {%0,%1,%2,%3}, [%4];"
        : "=r"(r[0]), "=r"(r[1]), "=r"(r[2]), "=r"(r[3]) : "r"(addr));
}
__device__ __forceinline__ void hmma(float* c, const uint32_t* a, const uint32_t* b) {
    asm volatile("mma.sync.aligned.m16n8k16.row.col.f32.f16.f16.f32 "
        "{%0,%1,%2,%3}, {%4,%5,%6,%7}, {%8,%9}, {%0,%1,%2,%3};"
        : "+f"(c[0]), "+f"(c[1]), "+f"(c[2]), "+f"(c[3])
        : "r"(a[0]), "r"(a[1]), "r"(a[2]), "r"(a[3]), "r"(b[0]), "r"(b[1]));
}
// 16B-granule XOR swizzle within 128B rows (conflict-free ldmatrix)
__device__ __forceinline__ uint32_t swzoff(int r, int ci) {
    uint32_t o = (uint32_t)(r * 128 + ci * 16);
    return o ^ ((o >> 3) & 0x70);
}

// ---------------- threefry / jax randint ----------------
__device__ __forceinline__ unsigned rotl32(unsigned x, int r) { return (x << r) | (x >> (32 - r)); }
__device__ __forceinline__ void tf2x32(unsigned k0, unsigned k1, unsigned& x0, unsigned& x1) {
    const unsigned ks2 = 0x1BD11BDAu ^ k0 ^ k1;
#define TF_RND(r) { x0 += x1; x1 = rotl32(x1, (r)); x1 ^= x0; }
    x0 += k0; x1 += k1;
    TF_RND(13) TF_RND(15) TF_RND(26) TF_RND(6)
    x0 += k1;  x1 += ks2 + 1u;
    TF_RND(17) TF_RND(29) TF_RND(16) TF_RND(24)
    x0 += ks2; x1 += k0 + 2u;
    TF_RND(13) TF_RND(15) TF_RND(26) TF_RND(6)
    x0 += k0;  x1 += k1 + 3u;
    TF_RND(17) TF_RND(29) TF_RND(16) TF_RND(24)
    x0 += k1;  x1 += ks2 + 4u;
    TF_RND(13) TF_RND(15) TF_RND(26) TF_RND(6)
    x0 += ks2; x1 += k0 + 5u;
#undef TF_RND
}
__device__ unsigned jax_randint_idx(int i) {
    unsigned s0 = 0u, s1 = 1u;
    tf2x32(0u, 42u, s0, s1);
    unsigned x0 = 0u, x1 = (unsigned)i;
    tf2x32(s0, s1, x0, x1);
    return (x0 ^ x1) & 0x1FFFFu;
}

// ---------------- fp16 scaled double split ----------------
__device__ __forceinline__ void hsplit(float a, unsigned short& u0, unsigned short& u1) {
    __half p0 = __float2half_rn(a);
    float r = a - __half2float(p0);
    __half p1 = __float2half_rn(r * CORR_SCALE);
    u0 = __half_as_ushort(p0);
    u1 = __half_as_ushort(p1);
}

// ---------------- simple kernels ----------------
__global__ void k_zero() {
    int i = blockIdx.x * blockDim.x + threadIdx.x;
    if (i < NCODES * DDIM) g_esum[i] = 0.0f;
    if (i < NCODES)        g_counts[i] = 0.0f;
}

// normalize h rows and write scaled fp16 splits (warp per row)
__global__ void k_prep_h(const float* __restrict__ h) {
    int w = (blockIdx.x * blockDim.x + threadIdx.x) >> 5;
    int lane = threadIdx.x & 31;
    if (w >= NROWS) return;
    const float4* row = (const float4*)(h + (size_t)w * DDIM);
    float4 v[2];
    float s = 0.0f;
#pragma unroll
    for (int t = 0; t < 2; t++) {
        v[t] = row[lane + 32 * t];
        s += v[t].x * v[t].x + v[t].y * v[t].y + v[t].z * v[t].z + v[t].w * v[t].w;
    }
#pragma unroll
    for (int o = 16; o; o >>= 1) s += __shfl_xor_sync(0xFFFFFFFFu, s, o);
    float rs = (float)(1.0 / sqrt((double)fmaxf(s, 1e-12f)));
#pragma unroll
    for (int t = 0; t < 2; t++) {
        int f = lane + 32 * t;
        float a[4] = { v[t].x * rs, v[t].y * rs, v[t].z * rs, v[t].w * rs };
        unsigned short u0[4], u1[4];
#pragma unroll
        for (int e = 0; e < 4; e++) hsplit(a[e], u0[e], u1[e]);
        size_t off = (size_t)w * DDIM + f * 4;
        *(uint2*)(g_h0 + off) = make_uint2((uint32_t)u0[0] | ((uint32_t)u0[1] << 16),
                                           (uint32_t)u0[2] | ((uint32_t)u0[3] << 16));
        *(uint2*)(g_h1 + off) = make_uint2((uint32_t)u1[0] | ((uint32_t)u1[1] << 16),
                                           (uint32_t)u1[2] | ((uint32_t)u1[3] << 16));
    }
}

// normalize embed rows and write scaled fp16 splits
__global__ void k_prep_embed(const float* __restrict__ e) {
    int w = (blockIdx.x * blockDim.x + threadIdx.x) >> 5;
    int lane = threadIdx.x & 31;
    if (w >= NCODES) return;
    const float* row = e + (size_t)w * DDIM;
    float s = 0.0f;
#pragma unroll
    for (int t = 0; t < 8; t++) { float v = row[lane + 32 * t]; s += v * v; }
#pragma unroll
    for (int o = 16; o; o >>= 1) s += __shfl_xor_sync(0xFFFFFFFFu, s, o);
    float rs = (float)(1.0 / sqrt((double)fmaxf(s, 1e-12f)));
#pragma unroll
    for (int t = 0; t < 8; t++) {
        int d = lane + 32 * t;
        unsigned short u0, u1;
        hsplit(row[d] * rs, u0, u1);
        size_t idx = (size_t)w * DDIM + d;
        g_e0[idx] = __ushort_as_half(u0);
        g_e1[idx] = __ushort_as_half(u1);
    }
}

// ---------------- HMMA argmin GEMM ----------------
// buffer: A0(16K) A1(16K) B0(16K) B1(16K); double buffered.
#define BUF_BYTES 65536u
#define SMEM_DYN  (2u * BUF_BYTES + 2048u)

__device__ __forceinline__ void issue_loads(int tid, size_t rowBase, int s2, uint32_t buf) {
    const int cc = s2 >> 2, kt = s2 & 3;
    const __half* hb[2] = { g_h0, g_h1 };
    const __half* eb[2] = { g_e0, g_e1 };
#pragma unroll
    for (int t = 0; t < 2; t++) {
#pragma unroll
        for (int q = 0; q < 4; q++) {
            int idx = tid + 256 * q;           // 1024 granules of 16B per split
            int r = idx >> 3, ci = idx & 7;
            uint32_t sw = swzoff(r, ci);
            cpa16(buf + t * 16384u + sw,
                  hb[t] + (rowBase + r) * DDIM + kt * 64 + ci * 8);
            cpa16(buf + 32768u + t * 16384u + sw,
                  eb[t] + (size_t)(cc * 128 + r) * DDIM + kt * 64 + ci * 8);
        }
    }
}

__global__ __launch_bounds__(256, 1) void k_argmin_mma(float* __restrict__ out) {
    extern __shared__ __align__(1024) char smem[];
    const uint32_t sb = smem_u32(smem);
    const int tid = threadIdx.x, lane = tid & 31, w = tid >> 5;
    const size_t rowBase = (size_t)blockIdx.x * 128;

    const int mbase = (w & 3) * 32;    // warp's 32 rows within 128
    const int nbw   = (w >> 2) * 64;   // warp's 64 codes within 128-chunk

    float accM[2][8][4], accC[2][8][4];
    float bestV[4]; int bestI[4];
#pragma unroll
    for (int b = 0; b < 4; b++) { bestV[b] = 3.4e38f; bestI[b] = 0; }

    // ldmatrix lane address components
    const int arow = mbase + (lane & 7) + ((lane >> 3) & 1) * 8;
    const int aciX = (lane >> 4);
    const int brow = nbw + (lane & 7) + ((lane >> 4) << 3);
    const int bciX = ((lane >> 3) & 1);

    issue_loads(tid, rowBase, 0, sb);
    CP_COMMIT(); CP_WAIT0(); __syncthreads();

    for (int s = 0; s < 32; s++) {              // s = cc*4 + kt
        const uint32_t buf = sb + (uint32_t)(s & 1) * BUF_BYTES;
        if ((s & 3) == 0) {
#pragma unroll
            for (int mi = 0; mi < 2; mi++)
#pragma unroll
                for (int nj = 0; nj < 8; nj++)
#pragma unroll
                    for (int rr = 0; rr < 4; rr++) { accM[mi][nj][rr] = 0.0f; accC[mi][nj][rr] = 0.0f; }
        }
        if (s < 31) {
            issue_loads(tid, rowBase, s + 1, sb + (uint32_t)((s + 1) & 1) * BUF_BYTES);
            CP_COMMIT();
        }

#pragma unroll
        for (int ks = 0; ks < 4; ks++) {
            uint32_t Aoff = swzoff(arow, ks * 2 + aciX);
            uint32_t A[2][2][4];
#pragma unroll
            for (int t = 0; t < 2; t++) {
                ldmx4(A[t][0], buf + t * 16384u + Aoff);
                ldmx4(A[t][1], buf + t * 16384u + Aoff + 2048u);
            }
            uint32_t Boff = swzoff(brow, ks * 2 + bciX);
#pragma unroll
            for (int p = 0; p < 4; p++) {
                uint32_t B0[4], B1[4];
                ldmx4(B0, buf + 32768u + Boff + p * 2048u);
                ldmx4(B1, buf + 49152u + Boff + p * 2048u);
#pragma unroll
                for (int mi = 0; mi < 2; mi++) {
                    hmma(accM[mi][2 * p],     A[0][mi], &B0[0]);
                    hmma(accM[mi][2 * p + 1], A[0][mi], &B0[2]);
                    hmma(accC[mi][2 * p],     A[0][mi], &B1[0]);
                    hmma(accC[mi][2 * p + 1], A[0][mi], &B1[2]);
                    hmma(accC[mi][2 * p],     A[1][mi], &B0[0]);
                    hmma(accC[mi][2 * p + 1], A[1][mi], &B0[2]);
                }
            }
        }

        if ((s & 3) == 3) {                 // chunk done: fold argmin
            const int cc = s >> 2;
#pragma unroll
            for (int mi = 0; mi < 2; mi++)
#pragma unroll
                for (int nj = 0; nj < 8; nj++) {
                    int col0 = cc * 128 + nbw + nj * 8 + (lane & 3) * 2;
                    float d0 = 1.0f - (accM[mi][nj][0] + accC[mi][nj][0] * CORR_INV);
                    float d1 = 1.0f - (accM[mi][nj][1] + accC[mi][nj][1] * CORR_INV);
                    float d2 = 1.0f - (accM[mi][nj][2] + accC[mi][nj][2] * CORR_INV);
                    float d3 = 1.0f - (accM[mi][nj][3] + accC[mi][nj][3] * CORR_INV);
                    int b0 = 2 * mi, b1 = 2 * mi + 1;
                    if (d0 < bestV[b0]) { bestV[b0] = d0; bestI[b0] = col0; }
                    if (d1 < bestV[b0]) { bestV[b0] = d1; bestI[b0] = col0 + 1; }
                    if (d2 < bestV[b1]) { bestV[b1] = d2; bestI[b1] = col0; }
                    if (d3 < bestV[b1]) { bestV[b1] = d3; bestI[b1] = col0 + 1; }
                }
        }

        if (s < 31) { CP_WAIT0(); __syncthreads(); }
    }

    // quad reduce: lanes 4q..4q+3 share the same 4 rows
#pragma unroll
    for (int off = 1; off <= 2; off <<= 1) {
#pragma unroll
        for (int b = 0; b < 4; b++) {
            float v = __shfl_down_sync(0xFFFFFFFFu, bestV[b], off);
            int   i = __shfl_down_sync(0xFFFFFFFFu, bestI[b], off);
            if (v < bestV[b] || (v == bestV[b] && i < bestI[b])) { bestV[b] = v; bestI[b] = i; }
        }
    }
    float* redV = (float*)(smem + 2 * BUF_BYTES);
    int*   redI = (int*)(smem + 2 * BUF_BYTES + 1024);
    if ((lane & 3) == 0) {
#pragma unroll
        for (int b = 0; b < 4; b++) {
            int row = mbase + (b >> 1) * 16 + (lane >> 2) + (b & 1) * 8;
            int half = w >> 2;
            redV[row * 2 + half] = bestV[b];
            redI[row * 2 + half] = bestI[b];
        }
    }
    __syncthreads();
    if (tid < 128) {
        float v0 = redV[tid * 2], v1 = redV[tid * 2 + 1];
        int i0 = redI[tid * 2], i1 = redI[tid * 2 + 1];
        int bi = (v1 < v0 || (v1 == v0 && i1 < i0)) ? i1 : i0;
        g_zid[rowBase + tid] = bi;
        out[OFF_ZID + rowBase + tid] = (float)bi;
    }
}

// ---------------- per-row assign / scatter ----------------
__global__ __launch_bounds__(256) void k_assign(const float* __restrict__ h,
                                                const float* __restrict__ embed,
                                                float* __restrict__ out) {
    __shared__ float wsum[8];
    int lane = threadIdx.x & 31, w = threadIdx.x >> 5;
    size_t row = (size_t)blockIdx.x * 8 + w;
    int code = g_zid[row];
    const float4* hr = (const float4*)(h + row * DDIM);
    const float4* er = (const float4*)(embed + (size_t)code * DDIM);
    float*  zq   = out + OFF_ZQ + row * DDIM;            // 4B-aligned only
    float4* zqst = (float4*)(out + OFF_ZQST + row * DDIM);
    float acc = 0.0f;
#pragma unroll
    for (int t = 0; t < 2; t++) {
        int d4 = lane + 32 * t;
        float4 hv = hr[d4], ev = er[d4];
        zq[d4 * 4 + 0] = ev.x; zq[d4 * 4 + 1] = ev.y;
        zq[d4 * 4 + 2] = ev.z; zq[d4 * 4 + 3] = ev.w;
        float4 st;
        st.x = hv.x + (ev.x - hv.x); st.y = hv.y + (ev.y - hv.y);
        st.z = hv.z + (ev.z - hv.z); st.w = hv.w + (ev.w - hv.w);
        zqst[d4] = st;
        float dx = hv.x - ev.x, dy = hv.y - ev.y, dz = hv.z - ev.z, dw = hv.w - ev.w;
        acc += dx * dx + dy * dy + dz * dz + dw * dw;
        float* es = &g_esum[(size_t)code * DDIM + d4 * 4];
        atomicAdd(es + 0, hv.x); atomicAdd(es + 1, hv.y);
        atomicAdd(es + 2, hv.z); atomicAdd(es + 3, hv.w);
    }
#pragma unroll
    for (int o = 16; o; o >>= 1) acc += __shfl_xor_sync(0xFFFFFFFFu, acc, o);
    if (lane == 0) {
        wsum[w] = acc;
        atomicAdd(&g_counts[code], 1.0f);
    }
    __syncthreads();
    if (threadIdx.x == 0) {
        double sum = 0.0;
#pragma unroll
        for (int i = 0; i < 8; i++) sum += (double)wsum[i];
        g_losspart[blockIdx.x] = sum;
    }
}

// ---------------- per-code scalars ----------------
__global__ void k_final_a(const float* __restrict__ cs_in, float* __restrict__ out) {
    __shared__ double sd[1024];
    int t = threadIdx.x;
    float c = g_counts[t];
    float ncs = cs_in[t] * DECAYC + c * (1.0f - DECAYC);

    sd[t] = (double)ncs; __syncthreads();
    for (int o = 512; o; o >>= 1) { if (t < o) sd[t] += sd[t + o]; __syncthreads(); }
    double n = sd[0]; __syncthreads();

    float usage = c / 131072.0f;
    float term = (usage > 0.0f) ? usage * logf(usage) : 0.0f;
    sd[t] = (double)term; __syncthreads();
    for (int o = 512; o; o >>= 1) { if (t < o) sd[t] += sd[t + o]; __syncthreads(); }
    float ent = -(float)sd[0]; __syncthreads();

    double lp = 0.0;
    for (int i = t; i < 16384; i += 1024) lp += g_losspart[i];
    sd[t] = lp; __syncthreads();
    for (int o = 512; o; o >>= 1) { if (t < o) sd[t] += sd[t + o]; __syncthreads(); }
    double loss_sum = sd[0];

    float nf = (float)n;
    float meanv = (float)(n / 1024.0);
    float cs_sm = (ncs + EPSC) / (nf + 1024.0f * EPSC) * nf;
    float den = fmaxf(cs_sm, EPSC);
    bool dead = (ncs / (131072.0f + EPSC)) < 0.01f;

    g_den[t] = den;
    g_src[t] = dead ? (int)jax_randint_idx(t) : -1;
    out[OFF_NCS + t] = dead ? fmaxf(meanv, 1.0f) : ncs;

    if (t == 0) {
        out[OFF_LOSS] = (float)(loss_sum / (double)((size_t)NROWS * DDIM));
        out[OFF_PPL]  = expf(ent);
    }
}

__global__ void k_final_b(const float* __restrict__ h, const float* __restrict__ ea_in,
                          float* __restrict__ out) {
    int k = blockIdx.x;
    int d = threadIdx.x;
    size_t idx = (size_t)k * DDIM + d;
    float nea = ea_in[idx] * DECAYC + g_esum[idx] * (1.0f - DECAYC);
    out[OFF_NEA + idx] = nea;
    int src = g_src[k];
    float ne = (src >= 0) ? h[(size_t)src * DDIM + d] : nea / g_den[k];
    out[OFF_NEMB + idx] = ne;
}

// ---------------- launch ----------------
extern "C" void kernel_launch(void* const* d_in, const int* in_sizes, int n_in,
                              void* d_out, int out_size) {
    const float* h     = (const float*)d_in[0];
    const float* embed = (const float*)d_in[1];
    const float* cs    = (const float*)d_in[2];
    const float* ea    = (const float*)d_in[3];
    float* out = (float*)d_out;

    static int smem_set = 0;
    if (!smem_set) {
        cudaFuncSetAttribute(k_argmin_mma, cudaFuncAttributeMaxDynamicSharedMemorySize, SMEM_DYN);
        smem_set = 1;
    }

    k_zero<<<1024, 256>>>();
    k_prep_h<<<16384, 256>>>(h);
    k_prep_embed<<<128, 256>>>(embed);
    k_argmin_mma<<<1024, 256, SMEM_DYN>>>(out);
    k_assign<<<16384, 256>>>(h, embed, out);
    k_final_a<<<1, 1024>>>(cs, out);
    k_final_b<<<1024, 256>>>(h, ea, out);
}

// round 11
// speedup vs baseline: 2.5274x; 1.0121x over previous
#include <cuda_runtime.h>
#include <cuda_fp16.h>
#include <math.h>
#include <stdint.h>

// ---------------- problem constants ----------------
#define NROWS   131072
#define DDIM    256
#define NCODES  1024
#define EPSC    1e-5f
#define DECAYC  0.99f

// ---------------- output layout (float32, reference tuple order, flattened) ----------------
#define OFF_ZQST 0ULL
#define OFF_ZID  33554432ULL
#define OFF_LOSS 33685504ULL
#define OFF_ZQ   33685505ULL
#define OFF_NEMB 67239937ULL
#define OFF_NCS  67502081ULL
#define OFF_NEA  67503105ULL
#define OFF_PPL  67765249ULL

#define CORR_SCALE 1024.0f
#define CORR_INV   0.0009765625f   // 2^-10

// ---------------- device scratch (static: no allocation allowed) ----------------
static __device__ __half g_h0[NROWS * DDIM];    // fp16(normalized h)
static __device__ __half g_h1[NROWS * DDIM];    // fp16((hn - h0) * 2^10)
static __device__ __half g_e0[NCODES * DDIM];   // fp16(normalized embed)
static __device__ __half g_e1[NCODES * DDIM];   // fp16((en - e0) * 2^10)
static __device__ int    g_zid[NROWS];
static __device__ int    g_icnt[NCODES];        // int histogram of z_id
static __device__ int    g_cursor[NCODES];      // prefix offsets -> end offsets
static __device__ int    g_csr[NROWS];          // row ids grouped by code
static __device__ float  g_esum[NCODES * DDIM];
static __device__ double g_losspart[16384];
static __device__ float  g_den[NCODES];
static __device__ int    g_src[NCODES];

// ---------------- PTX helpers (baseline sm_80+ features only) ----------------
__device__ __forceinline__ uint32_t smem_u32(const void* p) {
    uint32_t a;
    asm("{ .reg .u64 t; cvta.to.shared.u64 t, %1; cvt.u32.u64 %0, t; }" : "=r"(a) : "l"(p));
    return a;
}
__device__ __forceinline__ void cpa16(uint32_t dst, const void* src) {
    asm volatile("cp.async.cg.shared.global [%0], [%1], 16;" :: "r"(dst), "l"(src) : "memory");
}
#define CP_COMMIT() asm volatile("cp.async.commit_group;" ::: "memory")
#define CP_WAIT0()  asm volatile("cp.async.wait_group 0;" ::: "memory")

__device__ __forceinline__ void ldmx4(uint32_t* r, uint32_t addr) {
    asm volatile("ldmatrix.sync.aligned.m8n8.x4.shared.b16 {%0,%1,%2,%3}, [%4];"
        : "=r"(r[0]), "=r"(r[1]), "=r"(r[2]), "=r"(r[3]) : "r"(addr));
}
__device__ __forceinline__ void hmma(float* c, const uint32_t* a, const uint32_t* b) {
    asm volatile("mma.sync.aligned.m16n8k16.row.col.f32.f16.f16.f32 "
        "{%0,%1,%2,%3}, {%4,%5,%6,%7}, {%8,%9}, {%0,%1,%2,%3};"
        : "+f"(c[0]), "+f"(c[1]), "+f"(c[2]), "+f"(c[3])
        : "r"(a[0]), "r"(a[1]), "r"(a[2]), "r"(a[3]), "r"(b[0]), "r"(b[1]));
}
// 16B-granule XOR swizzle within 128B rows (conflict-free ldmatrix)
__device__ __forceinline__ uint32_t swzoff(int r, int ci) {
    uint32_t o = (uint32_t)(r * 128 + ci * 16);
    return o ^ ((o >> 3) & 0x70);
}

// ---------------- threefry / jax randint ----------------
__device__ __forceinline__ unsigned rotl32(unsigned x, int r) { return (x << r) | (x >> (32 - r)); }
__device__ __forceinline__ void tf2x32(unsigned k0, unsigned k1, unsigned& x0, unsigned& x1) {
    const unsigned ks2 = 0x1BD11BDAu ^ k0 ^ k1;
#define TF_RND(r) { x0 += x1; x1 = rotl32(x1, (r)); x1 ^= x0; }
    x0 += k0; x1 += k1;
    TF_RND(13) TF_RND(15) TF_RND(26) TF_RND(6)
    x0 += k1;  x1 += ks2 + 1u;
    TF_RND(17) TF_RND(29) TF_RND(16) TF_RND(24)
    x0 += ks2; x1 += k0 + 2u;
    TF_RND(13) TF_RND(15) TF_RND(26) TF_RND(6)
    x0 += k0;  x1 += k1 + 3u;
    TF_RND(17) TF_RND(29) TF_RND(16) TF_RND(24)
    x0 += k1;  x1 += ks2 + 4u;
    TF_RND(13) TF_RND(15) TF_RND(26) TF_RND(6)
    x0 += ks2; x1 += k0 + 5u;
#undef TF_RND
}
__device__ unsigned jax_randint_idx(int i) {
    unsigned s0 = 0u, s1 = 1u;
    tf2x32(0u, 42u, s0, s1);
    unsigned x0 = 0u, x1 = (unsigned)i;
    tf2x32(s0, s1, x0, x1);
    return (x0 ^ x1) & 0x1FFFFu;
}

// ---------------- fp16 scaled double split ----------------
__device__ __forceinline__ void hsplit(float a, unsigned short& u0, unsigned short& u1) {
    __half p0 = __float2half_rn(a);
    float r = a - __half2float(p0);
    __half p1 = __float2half_rn(r * CORR_SCALE);
    u0 = __half_as_ushort(p0);
    u1 = __half_as_ushort(p1);
}

// ---------------- simple kernels ----------------
__global__ void k_zero() {
    int i = threadIdx.x;           // 1 block x 1024
    g_icnt[i] = 0;
}

// normalize h rows and write scaled fp16 splits (warp per row)
__global__ void k_prep_h(const float* __restrict__ h) {
    int w = (blockIdx.x * blockDim.x + threadIdx.x) >> 5;
    int lane = threadIdx.x & 31;
    if (w >= NROWS) return;
    const float4* row = (const float4*)(h + (size_t)w * DDIM);
    float4 v[2];
    float s = 0.0f;
#pragma unroll
    for (int t = 0; t < 2; t++) {
        v[t] = row[lane + 32 * t];
        s += v[t].x * v[t].x + v[t].y * v[t].y + v[t].z * v[t].z + v[t].w * v[t].w;
    }
#pragma unroll
    for (int o = 16; o; o >>= 1) s += __shfl_xor_sync(0xFFFFFFFFu, s, o);
    float rs = (float)(1.0 / sqrt((double)fmaxf(s, 1e-12f)));
#pragma unroll
    for (int t = 0; t < 2; t++) {
        int f = lane + 32 * t;
        float a[4] = { v[t].x * rs, v[t].y * rs, v[t].z * rs, v[t].w * rs };
        unsigned short u0[4], u1[4];
#pragma unroll
        for (int e = 0; e < 4; e++) hsplit(a[e], u0[e], u1[e]);
        size_t off = (size_t)w * DDIM + f * 4;
        *(uint2*)(g_h0 + off) = make_uint2((uint32_t)u0[0] | ((uint32_t)u0[1] << 16),
                                           (uint32_t)u0[2] | ((uint32_t)u0[3] << 16));
        *(uint2*)(g_h1 + off) = make_uint2((uint32_t)u1[0] | ((uint32_t)u1[1] << 16),
                                           (uint32_t)u1[2] | ((uint32_t)u1[3] << 16));
    }
}

// normalize embed rows and write scaled fp16 splits
__global__ void k_prep_embed(const float* __restrict__ e) {
    int w = (blockIdx.x * blockDim.x + threadIdx.x) >> 5;
    int lane = threadIdx.x & 31;
    if (w >= NCODES) return;
    const float* row = e + (size_t)w * DDIM;
    float s = 0.0f;
#pragma unroll
    for (int t = 0; t < 8; t++) { float v = row[lane + 32 * t]; s += v * v; }
#pragma unroll
    for (int o = 16; o; o >>= 1) s += __shfl_xor_sync(0xFFFFFFFFu, s, o);
    float rs = (float)(1.0 / sqrt((double)fmaxf(s, 1e-12f)));
#pragma unroll
    for (int t = 0; t < 8; t++) {
        int d = lane + 32 * t;
        unsigned short u0, u1;
        hsplit(row[d] * rs, u0, u1);
        size_t idx = (size_t)w * DDIM + d;
        g_e0[idx] = __ushort_as_half(u0);
        g_e1[idx] = __ushort_as_half(u1);
    }
}

// ---------------- HMMA argmin GEMM (unchanged from passing R10) ----------------
#define BUF_BYTES 65536u
#define SMEM_DYN  (2u * BUF_BYTES + 2048u)

__device__ __forceinline__ void issue_loads(int tid, size_t rowBase, int s2, uint32_t buf) {
    const int cc = s2 >> 2, kt = s2 & 3;
    const __half* hb[2] = { g_h0, g_h1 };
    const __half* eb[2] = { g_e0, g_e1 };
#pragma unroll
    for (int t = 0; t < 2; t++) {
#pragma unroll
        for (int q = 0; q < 4; q++) {
            int idx = tid + 256 * q;           // 1024 granules of 16B per split
            int r = idx >> 3, ci = idx & 7;
            uint32_t sw = swzoff(r, ci);
            cpa16(buf + t * 16384u + sw,
                  hb[t] + (rowBase + r) * DDIM + kt * 64 + ci * 8);
            cpa16(buf + 32768u + t * 16384u + sw,
                  eb[t] + (size_t)(cc * 128 + r) * DDIM + kt * 64 + ci * 8);
        }
    }
}

__global__ __launch_bounds__(256, 1) void k_argmin_mma(float* __restrict__ out) {
    extern __shared__ __align__(1024) char smem[];
    const uint32_t sb = smem_u32(smem);
    const int tid = threadIdx.x, lane = tid & 31, w = tid >> 5;
    const size_t rowBase = (size_t)blockIdx.x * 128;

    const int mbase = (w & 3) * 32;    // warp's 32 rows within 128
    const int nbw   = (w >> 2) * 64;   // warp's 64 codes within 128-chunk

    float accM[2][8][4], accC[2][8][4];
    float bestV[4]; int bestI[4];
#pragma unroll
    for (int b = 0; b < 4; b++) { bestV[b] = 3.4e38f; bestI[b] = 0; }

    const int arow = mbase + (lane & 7) + ((lane >> 3) & 1) * 8;
    const int aciX = (lane >> 4);
    const int brow = nbw + (lane & 7) + ((lane >> 4) << 3);
    const int bciX = ((lane >> 3) & 1);

    issue_loads(tid, rowBase, 0, sb);
    CP_COMMIT(); CP_WAIT0(); __syncthreads();

    for (int s = 0; s < 32; s++) {              // s = cc*4 + kt
        const uint32_t buf = sb + (uint32_t)(s & 1) * BUF_BYTES;
        if ((s & 3) == 0) {
#pragma unroll
            for (int mi = 0; mi < 2; mi++)
#pragma unroll
                for (int nj = 0; nj < 8; nj++)
#pragma unroll
                    for (int rr = 0; rr < 4; rr++) { accM[mi][nj][rr] = 0.0f; accC[mi][nj][rr] = 0.0f; }
        }
        if (s < 31) {
            issue_loads(tid, rowBase, s + 1, sb + (uint32_t)((s + 1) & 1) * BUF_BYTES);
            CP_COMMIT();
        }

#pragma unroll
        for (int ks = 0; ks < 4; ks++) {
            uint32_t Aoff = swzoff(arow, ks * 2 + aciX);
            uint32_t A[2][2][4];
#pragma unroll
            for (int t = 0; t < 2; t++) {
                ldmx4(A[t][0], buf + t * 16384u + Aoff);
                ldmx4(A[t][1], buf + t * 16384u + Aoff + 2048u);
            }
            uint32_t Boff = swzoff(brow, ks * 2 + bciX);
#pragma unroll
            for (int p = 0; p < 4; p++) {
                uint32_t B0[4], B1[4];
                ldmx4(B0, buf + 32768u + Boff + p * 2048u);
                ldmx4(B1, buf + 49152u + Boff + p * 2048u);
#pragma unroll
                for (int mi = 0; mi < 2; mi++) {
                    hmma(accM[mi][2 * p],     A[0][mi], &B0[0]);
                    hmma(accM[mi][2 * p + 1], A[0][mi], &B0[2]);
                    hmma(accC[mi][2 * p],     A[0][mi], &B1[0]);
                    hmma(accC[mi][2 * p + 1], A[0][mi], &B1[2]);
                    hmma(accC[mi][2 * p],     A[1][mi], &B0[0]);
                    hmma(accC[mi][2 * p + 1], A[1][mi], &B0[2]);
                }
            }
        }

        if ((s & 3) == 3) {                 // chunk done: fold argmin
            const int cc = s >> 2;
#pragma unroll
            for (int mi = 0; mi < 2; mi++)
#pragma unroll
                for (int nj = 0; nj < 8; nj++) {
                    int col0 = cc * 128 + nbw + nj * 8 + (lane & 3) * 2;
                    float d0 = 1.0f - (accM[mi][nj][0] + accC[mi][nj][0] * CORR_INV);
                    float d1 = 1.0f - (accM[mi][nj][1] + accC[mi][nj][1] * CORR_INV);
                    float d2 = 1.0f - (accM[mi][nj][2] + accC[mi][nj][2] * CORR_INV);
                    float d3 = 1.0f - (accM[mi][nj][3] + accC[mi][nj][3] * CORR_INV);
                    int b0 = 2 * mi, b1 = 2 * mi + 1;
                    if (d0 < bestV[b0]) { bestV[b0] = d0; bestI[b0] = col0; }
                    if (d1 < bestV[b0]) { bestV[b0] = d1; bestI[b0] = col0 + 1; }
                    if (d2 < bestV[b1]) { bestV[b1] = d2; bestI[b1] = col0; }
                    if (d3 < bestV[b1]) { bestV[b1] = d3; bestI[b1] = col0 + 1; }
                }
        }

        if (s < 31) { CP_WAIT0(); __syncthreads(); }
    }

#pragma unroll
    for (int off = 1; off <= 2; off <<= 1) {
#pragma unroll
        for (int b = 0; b < 4; b++) {
            float v = __shfl_down_sync(0xFFFFFFFFu, bestV[b], off);
            int   i = __shfl_down_sync(0xFFFFFFFFu, bestI[b], off);
            if (v < bestV[b] || (v == bestV[b] && i < bestI[b])) { bestV[b] = v; bestI[b] = i; }
        }
    }
    float* redV = (float*)(smem + 2 * BUF_BYTES);
    int*   redI = (int*)(smem + 2 * BUF_BYTES + 1024);
    if ((lane & 3) == 0) {
#pragma unroll
        for (int b = 0; b < 4; b++) {
            int row = mbase + (b >> 1) * 16 + (lane >> 2) + (b & 1) * 8;
            int half = w >> 2;
            redV[row * 2 + half] = bestV[b];
            redI[row * 2 + half] = bestI[b];
        }
    }
    __syncthreads();
    if (tid < 128) {
        float v0 = redV[tid * 2], v1 = redV[tid * 2 + 1];
        int i0 = redI[tid * 2], i1 = redI[tid * 2 + 1];
        int bi = (v1 < v0 || (v1 == v0 && i1 < i0)) ? i1 : i0;
        g_zid[rowBase + tid] = bi;
        out[OFF_ZID + rowBase + tid] = (float)bi;
    }
}

// ---------------- CSR build: count -> prefix -> fill ----------------
__global__ void k_count() {
    int i = blockIdx.x * blockDim.x + threadIdx.x;   // 131072 threads
    atomicAdd(&g_icnt[g_zid[i]], 1);
}

__global__ void k_prefix() {
    __shared__ int sm[1024];
    int t = threadIdx.x;
    int my = g_icnt[t];
    sm[t] = my;
    __syncthreads();
    for (int o = 1; o < 1024; o <<= 1) {
        int v = (t >= o) ? sm[t - o] : 0;
        __syncthreads();
        sm[t] += v;
        __syncthreads();
    }
    g_cursor[t] = sm[t] - my;     // exclusive prefix
}

__global__ void k_fill() {
    int i = blockIdx.x * blockDim.x + threadIdx.x;   // 131072 threads
    int code = g_zid[i];
    int t = atomicAdd(&g_cursor[code], 1);
    g_csr[t] = i;
}

// gather-sum per code: block per code, thread per dim (coalesced row reads)
__global__ __launch_bounds__(256) void k_sum(const float* __restrict__ h) {
    int c = blockIdx.x, d = threadIdx.x;
    int cnt = g_icnt[c];
    int start = g_cursor[c] - cnt;   // cursor is end offset after fill
    float acc = 0.0f;
    int j = 0;
    for (; j + 4 <= cnt; j += 4) {
        int r0 = g_csr[start + j],     r1 = g_csr[start + j + 1];
        int r2 = g_csr[start + j + 2], r3 = g_csr[start + j + 3];
        float v0 = h[(size_t)r0 * DDIM + d];
        float v1 = h[(size_t)r1 * DDIM + d];
        float v2 = h[(size_t)r2 * DDIM + d];
        float v3 = h[(size_t)r3 * DDIM + d];
        acc += v0 + v1 + v2 + v3;
    }
    for (; j < cnt; j++) acc += h[(size_t)g_csr[start + j] * DDIM + d];
    g_esum[(size_t)c * DDIM + d] = acc;
}

// ---------------- per-row assign (pure streaming now) ----------------
__global__ __launch_bounds__(256) void k_assign(const float* __restrict__ h,
                                                const float* __restrict__ embed,
                                                float* __restrict__ out) {
    __shared__ float wsum[8];
    int lane = threadIdx.x & 31, w = threadIdx.x >> 5;
    size_t row = (size_t)blockIdx.x * 8 + w;
    int code = g_zid[row];
    const float4* hr = (const float4*)(h + row * DDIM);
    const float4* er = (const float4*)(embed + (size_t)code * DDIM);
    float*  zq   = out + OFF_ZQ + row * DDIM;            // 4B-aligned only
    float4* zqst = (float4*)(out + OFF_ZQST + row * DDIM);
    float acc = 0.0f;
#pragma unroll
    for (int t = 0; t < 2; t++) {
        int d4 = lane + 32 * t;
        float4 hv = hr[d4], ev = er[d4];
        zq[d4 * 4 + 0] = ev.x; zq[d4 * 4 + 1] = ev.y;
        zq[d4 * 4 + 2] = ev.z; zq[d4 * 4 + 3] = ev.w;
        float4 st;
        st.x = hv.x + (ev.x - hv.x); st.y = hv.y + (ev.y - hv.y);
        st.z = hv.z + (ev.z - hv.z); st.w = hv.w + (ev.w - hv.w);
        zqst[d4] = st;
        float dx = hv.x - ev.x, dy = hv.y - ev.y, dz = hv.z - ev.z, dw = hv.w - ev.w;
        acc += dx * dx + dy * dy + dz * dz + dw * dw;
    }
#pragma unroll
    for (int o = 16; o; o >>= 1) acc += __shfl_xor_sync(0xFFFFFFFFu, acc, o);
    if (lane == 0) wsum[w] = acc;
    __syncthreads();
    if (threadIdx.x == 0) {
        double sum = 0.0;
#pragma unroll
        for (int i = 0; i < 8; i++) sum += (double)wsum[i];
        g_losspart[blockIdx.x] = sum;
    }
}

// ---------------- per-code scalars ----------------
__global__ void k_final_a(const float* __restrict__ cs_in, float* __restrict__ out) {
    __shared__ double sd[1024];
    int t = threadIdx.x;
    float c = (float)g_icnt[t];
    float ncs = cs_in[t] * DECAYC + c * (1.0f - DECAYC);

    sd[t] = (double)ncs; __syncthreads();
    for (int o = 512; o; o >>= 1) { if (t < o) sd[t] += sd[t + o]; __syncthreads(); }
    double n = sd[0]; __syncthreads();

    float usage = c / 131072.0f;
    float term = (usage > 0.0f) ? usage * logf(usage) : 0.0f;
    sd[t] = (double)term; __syncthreads();
    for (int o = 512; o; o >>= 1) { if (t < o) sd[t] += sd[t + o]; __syncthreads(); }
    float ent = -(float)sd[0]; __syncthreads();

    double lp = 0.0;
    for (int i = t; i < 16384; i += 1024) lp += g_losspart[i];
    sd[t] = lp; __syncthreads();
    for (int o = 512; o; o >>= 1) { if (t < o) sd[t] += sd[t + o]; __syncthreads(); }
    double loss_sum = sd[0];

    float nf = (float)n;
    float meanv = (float)(n / 1024.0);
    float cs_sm = (ncs + EPSC) / (nf + 1024.0f * EPSC) * nf;
    float den = fmaxf(cs_sm, EPSC);
    bool dead = (ncs / (131072.0f + EPSC)) < 0.01f;

    g_den[t] = den;
    g_src[t] = dead ? (int)jax_randint_idx(t) : -1;
    out[OFF_NCS + t] = dead ? fmaxf(meanv, 1.0f) : ncs;

    if (t == 0) {
        out[OFF_LOSS] = (float)(loss_sum / (double)((size_t)NROWS * DDIM));
        out[OFF_PPL]  = expf(ent);
    }
}

__global__ void k_final_b(const float* __restrict__ h, const float* __restrict__ ea_in,
                          float* __restrict__ out) {
    int k = blockIdx.x;
    int d = threadIdx.x;
    size_t idx = (size_t)k * DDIM + d;
    float nea = ea_in[idx] * DECAYC + g_esum[idx] * (1.0f - DECAYC);
    out[OFF_NEA + idx] = nea;
    int src = g_src[k];
    float ne = (src >= 0) ? h[(size_t)src * DDIM + d] : nea / g_den[k];
    out[OFF_NEMB + idx] = ne;
}

// ---------------- launch ----------------
extern "C" void kernel_launch(void* const* d_in, const int* in_sizes, int n_in,
                              void* d_out, int out_size) {
    const float* h     = (const float*)d_in[0];
    const float* embed = (const float*)d_in[1];
    const float* cs    = (const float*)d_in[2];
    const float* ea    = (const float*)d_in[3];
    float* out = (float*)d_out;

    static int smem_set = 0;
    if (!smem_set) {
        cudaFuncSetAttribute(k_argmin_mma, cudaFuncAttributeMaxDynamicSharedMemorySize, SMEM_DYN);
        smem_set = 1;
    }

    k_zero<<<1, 1024>>>();
    k_prep_h<<<16384, 256>>>(h);
    k_prep_embed<<<128, 256>>>(embed);
    k_argmin_mma<<<1024, 256, SMEM_DYN>>>(out);
    k_count<<<512, 256>>>();
    k_prefix<<<1, 1024>>>();
    k_fill<<<512, 256>>>();
    k_sum<<<1024, 256>>>(h);
    k_assign<<<16384, 256>>>(h, embed, out);
    k_final_a<<<1, 1024>>>(cs, out);
    k_final_b<<<1024, 256>>>(h, ea, out);
}